// round 7
// baseline (speedup 1.0000x reference)
#include <cuda_runtime.h>
#include <cuda_bf16.h>
#include <cstdint>

// LinearAttention B=4, N=4096, D=1024 fp32
// R7: projections via INT8 IMMA (radix-256 two-slice, 3 passes, s32 accum);
//     kv/out GEMMs stay bf16x3 mma.sync. Fused gate / split-transpose epilogues.

#define Bv 4
#define Nv 4096
#define Dv 1024
#define BNROWS (Bv*Nv)            // 16384

#define GT 256                    // 8 warps
#define ASZ 8192                  // 128 rows x 64B operand tile

#define STAGE1 (4*ASZ)            // stage: A1,A0,B1,B0 (or Ah,Al,Bh,Bl)
#define NST1 4
#define SMEM1 (NST1*STAGE1)       // 131072

#define QMAXF 32512.0f

#define SWZ64(x) ((x) ^ (((x) >> 3) & 0x30))

// ------------------------------ scratch -----------------------------------
__device__ __align__(16) char g_X1[(size_t)BNROWS*Dv];
__device__ __align__(16) char g_X0[(size_t)BNROWS*Dv];
__device__ __align__(16) char g_W1[4][1024*1024];
__device__ __align__(16) char g_W0[4][1024*1024];
__device__ __align__(16) float g_QLf[(size_t)BNROWS*Dv];     // ql fp32
__device__ __align__(16) __nv_bfloat16 g_QH [(size_t)BNROWS*Dv];
__device__ __align__(16) __nv_bfloat16 g_QLo[(size_t)BNROWS*Dv];
__device__ __align__(16) __nv_bfloat16 g_KTH[(size_t)Bv*Dv*Nv];
__device__ __align__(16) __nv_bfloat16 g_KTL[(size_t)Bv*Dv*Nv];
__device__ __align__(16) __nv_bfloat16 g_VTH[(size_t)Bv*Dv*Nv];
__device__ __align__(16) __nv_bfloat16 g_VTL[(size_t)Bv*Dv*Nv];
__device__ __align__(16) __nv_bfloat16 g_KVTH[(size_t)Bv*Dv*Dv];
__device__ __align__(16) __nv_bfloat16 g_KVTL[(size_t)Bv*Dv*Dv];
__device__ float g_absmax[8];     // [0]=x, [1..4]=w

// ------------------------------ helpers ------------------------------------
__device__ __forceinline__ uint32_t s2u(const void* p) {
    uint32_t a;
    asm("{ .reg .u64 t; cvta.to.shared.u64 t, %1; cvt.u32.u64 %0, t; }" : "=r"(a) : "l"(p));
    return a;
}
__device__ __forceinline__ void cpa16(uint32_t dst, const void* src) {
    asm volatile("cp.async.cg.shared.global [%0], [%1], 16;" :: "r"(dst), "l"(src));
}
#define CPC() asm volatile("cp.async.commit_group;" ::: "memory")

__device__ __forceinline__ void ldsm4(uint32_t* r, uint32_t addr) {
    asm volatile("ldmatrix.sync.aligned.m8n8.x4.shared.b16 {%0,%1,%2,%3}, [%4];"
                 : "=r"(r[0]), "=r"(r[1]), "=r"(r[2]), "=r"(r[3]) : "r"(addr));
}
__device__ __forceinline__ void mma16816(float* c, const uint32_t* a, const uint32_t* b) {
    asm volatile(
        "mma.sync.aligned.m16n8k16.row.col.f32.bf16.bf16.f32 "
        "{%0,%1,%2,%3}, {%4,%5,%6,%7}, {%8,%9}, {%0,%1,%2,%3};"
        : "+f"(c[0]), "+f"(c[1]), "+f"(c[2]), "+f"(c[3])
        : "r"(a[0]), "r"(a[1]), "r"(a[2]), "r"(a[3]), "r"(b[0]), "r"(b[1]));
}
__device__ __forceinline__ void mma_s8(int* c, const uint32_t* a, const uint32_t* b) {
    asm volatile(
        "mma.sync.aligned.m16n8k32.row.col.s32.s8.s8.s32 "
        "{%0,%1,%2,%3}, {%4,%5,%6,%7}, {%8,%9}, {%0,%1,%2,%3};"
        : "+r"(c[0]), "+r"(c[1]), "+r"(c[2]), "+r"(c[3])
        : "r"(a[0]), "r"(a[1]), "r"(a[2]), "r"(a[3]), "r"(b[0]), "r"(b[1]));
}

__device__ __forceinline__ uint32_t pack_hl(float f) {
    __nv_bfloat16 h = __float2bfloat16(f);
    __nv_bfloat16 l = __float2bfloat16(f - __bfloat162float(h));
    return ((uint32_t)__bfloat16_as_ushort(h) << 16) | __bfloat16_as_ushort(l);
}
__device__ __forceinline__ void split2pack(float f0, float f1, uint32_t& wh, uint32_t& wl) {
    __nv_bfloat16 h0 = __float2bfloat16(f0);
    __nv_bfloat16 h1 = __float2bfloat16(f1);
    __nv_bfloat16 l0 = __float2bfloat16(f0 - __bfloat162float(h0));
    __nv_bfloat16 l1 = __float2bfloat16(f1 - __bfloat162float(h1));
    wh = ((uint32_t)__bfloat16_as_ushort(h1) << 16) | __bfloat16_as_ushort(h0);
    wl = ((uint32_t)__bfloat16_as_ushort(l1) << 16) | __bfloat16_as_ushort(l0);
}
__device__ __forceinline__ void quant2(float v, float inv, int& q1, int& q0) {
    float s = fminf(fmaxf(v * inv, -QMAXF), QMAXF);
    int a1 = __float2int_rn(s * (1.0f/256.0f));
    int Ai = __float2int_rn(s);
    int a0 = Ai - (a1 << 8);
    if (a0 > 127)  { a0 -= 256; a1 += 1; }
    if (a0 < -128) { a0 += 256; a1 -= 1; }
    q1 = a1; q0 = a0;
}

// Split-transpose epilogue: 128x128 C tile -> OH/OL rows (bn+d), cols bm..
__device__ __forceinline__ void epi_splitT(
    const float (&acc)[4][4][4], char* sm,
    int wm, int wn, int lane, int tid,
    __nv_bfloat16* __restrict__ OH, __nv_bfloat16* __restrict__ OL,
    size_t base, int ldo)
{
    __syncthreads();
    uint32_t* s32 = (uint32_t*)sm;
#pragma unroll
    for (int mi = 0; mi < 4; mi++) {
        int r = wm + mi * 16 + (lane >> 2);
#pragma unroll
        for (int ni = 0; ni < 4; ni++) {
            int c = wn + ni * 8 + (lane & 3) * 2;
            s32[r * 133 + c]           = pack_hl(acc[mi][ni][0]);
            s32[r * 133 + c + 1]       = pack_hl(acc[mi][ni][1]);
            s32[(r + 8) * 133 + c]     = pack_hl(acc[mi][ni][2]);
            s32[(r + 8) * 133 + c + 1] = pack_hl(acc[mi][ni][3]);
        }
    }
    __syncthreads();
    int d = tid >> 1, nb = (tid & 1) * 64;
    __nv_bfloat16* rh = OH + base + (size_t)d * ldo + nb;
    __nv_bfloat16* rl = OL + base + (size_t)d * ldo + nb;
#pragma unroll
    for (int j = 0; j < 8; j++) {
        alignas(16) __nv_bfloat16 hb[8], lb[8];
#pragma unroll
        for (int i = 0; i < 8; i++) {
            uint32_t w = s32[(nb + j * 8 + i) * 133 + d];
            hb[i] = __ushort_as_bfloat16((unsigned short)(w >> 16));
            lb[i] = __ushort_as_bfloat16((unsigned short)(w & 0xFFFFu));
        }
        *(uint4*)(rh + j * 8) = *(const uint4*)hb;
        *(uint4*)(rl + j * 8) = *(const uint4*)lb;
    }
}

// --------------------- INT8 projection GEMM (3 passes) ----------------------
// C = sA*sB*(65536*H + 256*X), H = sum a1*b1, X = sum(a1*b0 + a0*b1).
// EPI 0: write fp32 C. EPI 1: gate with Cf (ql) then split straight bf16.
// EPI 2: split-transpose into per-batch [Dv][Nv].
template<int EPI>
__global__ __launch_bounds__(GT, 1)
void gemm_i8(const char* __restrict__ A1g, const char* __restrict__ A0g,
             const char* __restrict__ B1g, const char* __restrict__ B0g,
             int sidx, float* __restrict__ Cf,
             __nv_bfloat16* __restrict__ OH, __nv_bfloat16* __restrict__ OL,
             int M, int N, int Kg)
{
    extern __shared__ char sm[];
    const uint32_t smu = s2u(sm);
    const int tid = threadIdx.x, lane = tid & 31, wid = tid >> 5;
    const int bm = blockIdx.y * 128, bn = blockIdx.x * 128;
    const int wm = (wid & 1) * 64, wn = (wid >> 1) * 32;

    const int rr = tid >> 2, cg = tid & 3;
    const uint32_t so0 = SWZ64((uint32_t)(rr * 64 + cg * 16));
    const uint32_t so1 = SWZ64((uint32_t)((rr + 64) * 64 + cg * 16));
    const char* gA1 = A1g + (size_t)(bm + rr) * Kg + cg * 16;
    const char* gA0 = A0g + (size_t)(bm + rr) * Kg + cg * 16;
    const char* gB1 = B1g + (size_t)(bn + rr) * Kg + cg * 16;
    const char* gB0 = B0g + (size_t)(bn + rr) * Kg + cg * 16;
    const size_t rstep = (size_t)64 * Kg;

    uint32_t aoff[2][4], boff[2][2];
    {
        uint32_t arow = (uint32_t)(wm + (lane & 15));
        uint32_t acol = (uint32_t)((lane >> 4) * 16);
        uint32_t brow = (uint32_t)(wn + ((lane >> 4) << 3) + (lane & 7));
        uint32_t bcol = (uint32_t)(((lane >> 3) & 1) * 16);
#pragma unroll
        for (int ks = 0; ks < 2; ks++) {
#pragma unroll
            for (int mi = 0; mi < 4; mi++)
                aoff[ks][mi] = SWZ64((arow + mi * 16) * 64 + ks * 32 + acol);
#pragma unroll
            for (int g = 0; g < 2; g++)
                boff[ks][g] = SWZ64((brow + g * 16) * 64 + ks * 32 + bcol);
        }
    }

    int aH[4][4][4], aX[4][4][4];
#pragma unroll
    for (int mi = 0; mi < 4; mi++)
#pragma unroll
        for (int ni = 0; ni < 4; ni++)
#pragma unroll
            for (int j = 0; j < 4; j++) { aH[mi][ni][j] = 0; aX[mi][ni][j] = 0; }

    const int nch = Kg / 64;                 // 64 s8 per chunk
    auto load_stage = [&](int c) {
        const uint32_t st = smu + (uint32_t)(c & (NST1 - 1)) * STAGE1;
        const int k0 = c * 64;
        cpa16(st + so0,          gA1 + k0);
        cpa16(st + so1,          gA1 + k0 + rstep);
        cpa16(st + ASZ + so0,    gA0 + k0);
        cpa16(st + ASZ + so1,    gA0 + k0 + rstep);
        cpa16(st + 2*ASZ + so0,  gB1 + k0);
        cpa16(st + 2*ASZ + so1,  gB1 + k0 + rstep);
        cpa16(st + 3*ASZ + so0,  gB0 + k0);
        cpa16(st + 3*ASZ + so1,  gB0 + k0 + rstep);
        CPC();
    };

    load_stage(0); load_stage(1); load_stage(2);

    for (int c = 0; c < nch; ++c) {
        asm volatile("cp.async.wait_group 2;" ::: "memory");
        __syncthreads();
        if (c + 3 < nch) load_stage(c + 3);

        const uint32_t st = smu + (uint32_t)(c & (NST1 - 1)) * STAGE1;
#pragma unroll
        for (int ks = 0; ks < 2; ks++) {
            uint32_t a1[4][4], a0[4][4];
#pragma unroll
            for (int mi = 0; mi < 4; mi++) {
                ldsm4(a1[mi], st + aoff[ks][mi]);
                ldsm4(a0[mi], st + ASZ + aoff[ks][mi]);
            }
#pragma unroll
            for (int g = 0; g < 2; g++) {
                uint32_t tb1[4], tb0[4];
                ldsm4(tb1, st + 2*ASZ + boff[ks][g]);
                ldsm4(tb0, st + 3*ASZ + boff[ks][g]);
#pragma unroll
                for (int mi = 0; mi < 4; mi++) {
                    mma_s8(aH[mi][2*g],   a1[mi], tb1);
                    mma_s8(aX[mi][2*g],   a1[mi], tb0);
                    mma_s8(aX[mi][2*g],   a0[mi], tb1);
                    mma_s8(aH[mi][2*g+1], a1[mi], tb1 + 2);
                    mma_s8(aX[mi][2*g+1], a1[mi], tb0 + 2);
                    mma_s8(aX[mi][2*g+1], a0[mi], tb1 + 2);
                }
            }
        }
    }

    const float f = g_absmax[0] * g_absmax[sidx] * (1.0f / (QMAXF * QMAXF));
    float acc[4][4][4];
#pragma unroll
    for (int mi = 0; mi < 4; mi++)
#pragma unroll
        for (int ni = 0; ni < 4; ni++)
#pragma unroll
            for (int j = 0; j < 4; j++)
                acc[mi][ni][j] = f * (65536.0f * (float)aH[mi][ni][j]
                                      + 256.0f * (float)aX[mi][ni][j]);

    if (EPI == 0) {
#pragma unroll
        for (int mi = 0; mi < 4; mi++) {
            int rA = bm + wm + mi * 16 + (lane >> 2);
#pragma unroll
            for (int ni = 0; ni < 4; ni++) {
                int col = bn + wn + ni * 8 + (lane & 3) * 2;
                *(float2*)(Cf + (size_t)rA * N + col)       = make_float2(acc[mi][ni][0], acc[mi][ni][1]);
                *(float2*)(Cf + (size_t)(rA + 8) * N + col) = make_float2(acc[mi][ni][2], acc[mi][ni][3]);
            }
        }
    } else if (EPI == 1) {
        // gate with ql (Cf), split, straight bf16
#pragma unroll
        for (int mi = 0; mi < 4; mi++) {
            int r = bm + wm + mi * 16 + (lane >> 2);
#pragma unroll
            for (int ni = 0; ni < 4; ni++) {
                int c = bn + wn + ni * 8 + (lane & 3) * 2;
                float2 q0v = *(const float2*)(Cf + (size_t)r * N + c);
                float2 q1v = *(const float2*)(Cf + (size_t)(r + 8) * N + c);
                uint32_t wh, wl;
                split2pack(acc[mi][ni][0] * q0v.x, acc[mi][ni][1] * q0v.y, wh, wl);
                *(uint32_t*)(OH + (size_t)r * N + c) = wh;
                *(uint32_t*)(OL + (size_t)r * N + c) = wl;
                split2pack(acc[mi][ni][2] * q1v.x, acc[mi][ni][3] * q1v.y, wh, wl);
                *(uint32_t*)(OH + (size_t)(r + 8) * N + c) = wh;
                *(uint32_t*)(OL + (size_t)(r + 8) * N + c) = wl;
            }
        }
    } else {
        size_t batch = (size_t)(bm >> 12);
        size_t base = batch * (size_t)Dv * Nv + (size_t)bn * Nv + (bm & 4095);
        epi_splitT(acc, sm, wm, wn, lane, tid, OH, OL, base, Nv);
    }
}

// --------------------- bf16x3 GEMM (kv / out) -------------------------------
template<int MODE>   // 0: fp32 straight; 1: split-transpose
__global__ __launch_bounds__(GT, 1)
void gemm3(const __nv_bfloat16* __restrict__ Ahg, const __nv_bfloat16* __restrict__ Alg,
           const __nv_bfloat16* __restrict__ Bhg, const __nv_bfloat16* __restrict__ Blg,
           float* __restrict__ Cf,
           __nv_bfloat16* __restrict__ OH, __nv_bfloat16* __restrict__ OL,
           int M, int N, int Kg, long sA, long sB, long sO)
{
    extern __shared__ char sm[];
    const uint32_t smu = s2u(sm);
    const int tid = threadIdx.x, lane = tid & 31, wid = tid >> 5;
    const int bm = blockIdx.y * 128, bn = blockIdx.x * 128;
    const int wm = (wid & 1) * 64, wn = (wid >> 1) * 32;

    const __nv_bfloat16* Ah = Ahg + (size_t)blockIdx.z * sA;
    const __nv_bfloat16* Al = Alg + (size_t)blockIdx.z * sA;
    const __nv_bfloat16* Bh = Bhg + (size_t)blockIdx.z * sB;
    const __nv_bfloat16* Bl = Blg + (size_t)blockIdx.z * sB;

    const int rr = tid >> 2, cg = tid & 3;
    const uint32_t so0 = SWZ64((uint32_t)(rr * 64 + cg * 16));
    const uint32_t so1 = SWZ64((uint32_t)((rr + 64) * 64 + cg * 16));
    const __nv_bfloat16* gAh = Ah + (size_t)(bm + rr) * Kg + cg * 8;
    const __nv_bfloat16* gAl = Al + (size_t)(bm + rr) * Kg + cg * 8;
    const __nv_bfloat16* gBh = Bh + (size_t)(bn + rr) * Kg + cg * 8;
    const __nv_bfloat16* gBl = Bl + (size_t)(bn + rr) * Kg + cg * 8;
    const size_t rstep = (size_t)64 * Kg;

    uint32_t aoff[2][4], boff[2][2];
    {
        uint32_t arow = (uint32_t)(wm + (lane & 15));
        uint32_t acol = (uint32_t)((lane >> 4) * 16);
        uint32_t brow = (uint32_t)(wn + ((lane >> 4) << 3) + (lane & 7));
        uint32_t bcol = (uint32_t)(((lane >> 3) & 1) * 16);
#pragma unroll
        for (int ks = 0; ks < 2; ks++) {
#pragma unroll
            for (int mi = 0; mi < 4; mi++)
                aoff[ks][mi] = SWZ64((arow + mi * 16) * 64 + ks * 32 + acol);
#pragma unroll
            for (int g = 0; g < 2; g++)
                boff[ks][g] = SWZ64((brow + g * 16) * 64 + ks * 32 + bcol);
        }
    }

    float acc[4][4][4];
#pragma unroll
    for (int mi = 0; mi < 4; mi++)
#pragma unroll
        for (int ni = 0; ni < 4; ni++)
#pragma unroll
            for (int j = 0; j < 4; j++) acc[mi][ni][j] = 0.0f;

    const int nch = Kg / 32;
    auto load_stage = [&](int c) {
        const uint32_t st = smu + (uint32_t)(c & (NST1 - 1)) * STAGE1;
        const int k0 = c * 32;
        cpa16(st + so0,          gAh + k0);
        cpa16(st + so1,          gAh + k0 + rstep);
        cpa16(st + ASZ + so0,    gAl + k0);
        cpa16(st + ASZ + so1,    gAl + k0 + rstep);
        cpa16(st + 2*ASZ + so0,  gBh + k0);
        cpa16(st + 2*ASZ + so1,  gBh + k0 + rstep);
        cpa16(st + 3*ASZ + so0,  gBl + k0);
        cpa16(st + 3*ASZ + so1,  gBl + k0 + rstep);
        CPC();
    };

    load_stage(0); load_stage(1); load_stage(2);

    for (int c = 0; c < nch; ++c) {
        asm volatile("cp.async.wait_group 2;" ::: "memory");
        __syncthreads();
        if (c + 3 < nch) load_stage(c + 3);

        const uint32_t st = smu + (uint32_t)(c & (NST1 - 1)) * STAGE1;
#pragma unroll
        for (int ks = 0; ks < 2; ks++) {
            uint32_t ah[4][4], al[4][4];
#pragma unroll
            for (int mi = 0; mi < 4; mi++) {
                ldsm4(ah[mi], st + aoff[ks][mi]);
                ldsm4(al[mi], st + ASZ + aoff[ks][mi]);
            }
#pragma unroll
            for (int g = 0; g < 2; g++) {
                uint32_t tbh[4], tbl[4];
                ldsm4(tbh, st + 2*ASZ + boff[ks][g]);
                ldsm4(tbl, st + 3*ASZ + boff[ks][g]);
#pragma unroll
                for (int mi = 0; mi < 4; mi++) {
                    mma16816(acc[mi][2*g],   ah[mi], tbh);
                    mma16816(acc[mi][2*g],   ah[mi], tbl);
                    mma16816(acc[mi][2*g],   al[mi], tbh);
                    mma16816(acc[mi][2*g+1], ah[mi], tbh + 2);
                    mma16816(acc[mi][2*g+1], ah[mi], tbl + 2);
                    mma16816(acc[mi][2*g+1], al[mi], tbh + 2);
                }
            }
        }
    }

    if (MODE == 0) {
        float* Cb = Cf + (size_t)blockIdx.z * sO;
#pragma unroll
        for (int mi = 0; mi < 4; mi++) {
            int rA = bm + wm + mi * 16 + (lane >> 2);
#pragma unroll
            for (int ni = 0; ni < 4; ni++) {
                int col = bn + wn + ni * 8 + (lane & 3) * 2;
                *(float2*)(Cb + (size_t)rA * N + col)       = make_float2(acc[mi][ni][0], acc[mi][ni][1]);
                *(float2*)(Cb + (size_t)(rA + 8) * N + col) = make_float2(acc[mi][ni][2], acc[mi][ni][3]);
            }
        }
    } else {
        size_t base = (size_t)blockIdx.z * sO + (size_t)bn * M + bm;
        epi_splitT(acc, sm, wm, wn, lane, tid, OH, OL, base, M);
    }
}

// --------------------------- glue kernels ----------------------------------
__global__ void zero_scales() {
    if (threadIdx.x < 8) g_absmax[threadIdx.x] = 0.0f;
}

__global__ void absmax_k(const float* __restrict__ in, long n4, int slot) {
    __shared__ float red[32];
    float m = 0.0f;
    for (long i = (long)blockIdx.x * blockDim.x + threadIdx.x; i < n4;
         i += (long)gridDim.x * blockDim.x) {
        float4 f = ((const float4*)in)[i];
        m = fmaxf(m, fmaxf(fmaxf(fabsf(f.x), fabsf(f.y)), fmaxf(fabsf(f.z), fabsf(f.w))));
    }
#pragma unroll
    for (int o = 16; o > 0; o >>= 1)
        m = fmaxf(m, __shfl_xor_sync(0xFFFFFFFFu, m, o));
    if ((threadIdx.x & 31) == 0) red[threadIdx.x >> 5] = m;
    __syncthreads();
    if (threadIdx.x < 32) {
        m = (threadIdx.x < (blockDim.x >> 5)) ? red[threadIdx.x] : 0.0f;
#pragma unroll
        for (int o = 16; o > 0; o >>= 1)
            m = fmaxf(m, __shfl_xor_sync(0xFFFFFFFFu, m, o));
        if (threadIdx.x == 0)
            atomicMax((unsigned*)&g_absmax[slot], __float_as_uint(m));
    }
}

__global__ void quant_x(const float* __restrict__ in, char* __restrict__ O1,
                        char* __restrict__ O0) {
    const float inv = QMAXF / fmaxf(g_absmax[0], 1e-20f);
    size_t i = (size_t)blockIdx.x * blockDim.x + threadIdx.x;
    float4 f = ((const float4*)in)[i];
    int q1[4], q0[4];
    quant2(f.x, inv, q1[0], q0[0]); quant2(f.y, inv, q1[1], q0[1]);
    quant2(f.z, inv, q1[2], q0[2]); quant2(f.w, inv, q1[3], q0[3]);
    ((char4*)O1)[i] = make_char4((char)q1[0], (char)q1[1], (char)q1[2], (char)q1[3]);
    ((char4*)O0)[i] = make_char4((char)q0[0], (char)q0[1], (char)q0[2], (char)q0[3]);
}

// w[d][e] fp32 -> transposed s8 slices [e][d], z selects weight
__global__ void quant_wT(const float* w0, const float* w1, const float* w2, const float* w3,
                         char* __restrict__ O1, char* __restrict__ O0) {
    const float* in = (blockIdx.z == 0) ? w0 : (blockIdx.z == 1) ? w1
                     : (blockIdx.z == 2) ? w2 : w3;
    char* o1 = O1 + (size_t)blockIdx.z * Dv * Dv;
    char* o0 = O0 + (size_t)blockIdx.z * Dv * Dv;
    const float inv = QMAXF / fmaxf(g_absmax[1 + blockIdx.z], 1e-20f);
    __shared__ float t[32][33];
    int c0 = blockIdx.x * 32, r0 = blockIdx.y * 32;
    int tx = threadIdx.x, ty = threadIdx.y;
#pragma unroll
    for (int i = 0; i < 4; i++)
        t[ty + i*8][tx] = in[(size_t)(r0 + ty + i*8) * Dv + c0 + tx];
    __syncthreads();
#pragma unroll
    for (int i = 0; i < 4; i++) {
        int oc = c0 + ty + i*8, od = r0 + tx;
        int q1, q0; quant2(t[tx][ty + i*8], inv, q1, q0);
        o1[(size_t)oc * Dv + od] = (char)q1;
        o0[(size_t)oc * Dv + od] = (char)q0;
    }
}

// ------------------------------- launch ------------------------------------
extern "C" void kernel_launch(void* const* d_in, const int* in_sizes, int n_in,
                              void* d_out, int out_size) {
    const float* x   = (const float*)d_in[0];
    const float* w[4] = { (const float*)d_in[1], (const float*)d_in[2],
                          (const float*)d_in[3], (const float*)d_in[4] };
    float* out = (float*)d_out;

    char *X1,*X0,*W1,*W0;
    float *QLf;
    __nv_bfloat16 *QH,*QLo,*KTH,*KTL,*VTH,*VTL,*KVTH,*KVTL;
    cudaGetSymbolAddress((void**)&X1,  g_X1);   cudaGetSymbolAddress((void**)&X0,  g_X0);
    cudaGetSymbolAddress((void**)&W1,  g_W1);   cudaGetSymbolAddress((void**)&W0,  g_W0);
    cudaGetSymbolAddress((void**)&QLf, g_QLf);
    cudaGetSymbolAddress((void**)&QH,  g_QH);   cudaGetSymbolAddress((void**)&QLo, g_QLo);
    cudaGetSymbolAddress((void**)&KTH, g_KTH);  cudaGetSymbolAddress((void**)&KTL, g_KTL);
    cudaGetSymbolAddress((void**)&VTH, g_VTH);  cudaGetSymbolAddress((void**)&VTL, g_VTL);
    cudaGetSymbolAddress((void**)&KVTH,g_KVTH); cudaGetSymbolAddress((void**)&KVTL,g_KVTL);

    cudaFuncSetAttribute(gemm_i8<0>, cudaFuncAttributeMaxDynamicSharedMemorySize, SMEM1);
    cudaFuncSetAttribute(gemm_i8<1>, cudaFuncAttributeMaxDynamicSharedMemorySize, SMEM1);
    cudaFuncSetAttribute(gemm_i8<2>, cudaFuncAttributeMaxDynamicSharedMemorySize, SMEM1);
    cudaFuncSetAttribute(gemm3<0>,   cudaFuncAttributeMaxDynamicSharedMemorySize, SMEM1);
    cudaFuncSetAttribute(gemm3<1>,   cudaFuncAttributeMaxDynamicSharedMemorySize, SMEM1);

    const size_t DDe = (size_t)Dv * Dv;
    const size_t PNe = (size_t)BNROWS * Dv;
    dim3 tb32(32, 8);

    // 1) scales
    zero_scales<<<1, 32>>>();
    absmax_k<<<1024, 256>>>(x, (long)(PNe / 4), 0);
    for (int i = 0; i < 4; i++)
        absmax_k<<<256, 256>>>(w[i], (long)(DDe / 4), 1 + i);

    // 2) quantize
    quant_x<<<(unsigned)(PNe / 4 / 256), 256>>>(x, X1, X0);
    quant_wT<<<dim3(Dv/32, Dv/32, 4), tb32>>>(w[0], w[1], w[2], w[3], W1, W0);

    // 3) projections (int8): ql -> fp32; qr gates -> q split; k,v -> splitT
    dim3 gproj(Dv/128, BNROWS/128);
    gemm_i8<0><<<gproj, GT, SMEM1>>>(X1, X0, W1 + 0*DDe, W0 + 0*DDe, 1,
                                     QLf, nullptr, nullptr, BNROWS, Dv, Dv);
    gemm_i8<1><<<gproj, GT, SMEM1>>>(X1, X0, W1 + 1*DDe, W0 + 1*DDe, 2,
                                     QLf, QH, QLo, BNROWS, Dv, Dv);
    gemm_i8<2><<<gproj, GT, SMEM1>>>(X1, X0, W1 + 2*DDe, W0 + 2*DDe, 3,
                                     nullptr, KTH, KTL, BNROWS, Dv, Dv);
    gemm_i8<2><<<gproj, GT, SMEM1>>>(X1, X0, W1 + 3*DDe, W0 + 3*DDe, 4,
                                     nullptr, VTH, VTL, BNROWS, Dv, Dv);

    // 4) kv[b] = k^T@v (bf16x3) -> kv^T split
    gemm3<1><<<dim3(Dv/128, Dv/128, Bv), GT, SMEM1>>>(
        KTH, KTL, VTH, VTL, nullptr, KVTH, KVTL,
        Dv, Dv, Nv, (long)Dv*Nv, (long)Dv*Nv, (long)DDe);

    // 5) out[b] = q@kv (bf16x3) -> fp32
    gemm3<0><<<dim3(Dv/128, Nv/128, Bv), GT, SMEM1>>>(
        QH, QLo, KVTH, KVTL, out, nullptr, nullptr,
        Nv, Dv, Dv, (long)Nv*Dv, (long)DDe, (long)Nv*Dv);
}

// round 8
// speedup vs baseline: 3.1241x; 3.1241x over previous
#include <cuda_runtime.h>
#include <cuda_fp16.h>
#include <cstdint>

// LinearAttention B=4, N=4096, D=1024 fp32
// R8: fp16 2-pass GEMMs (A split hi/lo — exact; B single fp16), mma.sync.
//     Fused gate / split-transpose epilogues. ~2/3 the MMA work of bf16x3.

#define Bv 4
#define Nv 4096
#define Dv 1024
#define BNROWS (Bv*Nv)            // 16384

#define GT 256                    // 8 warps
#define ASZ 8192                  // 128 rows x 64B operand tile

#define STG1 (3*ASZ)              // single-B stage: Ah,Al,B
#define NST 4
#define SMEM1 (NST*STG1)          // 98304
#define STG2 (4*ASZ)              // dual-B stage: Ah,Al,B1,B2
#define SMEM2 (NST*STG2)          // 131072

#define SWZ64(x) ((x) ^ (((x) >> 3) & 0x30))

// ------------------------------ scratch -----------------------------------
__device__ __align__(16) __half g_XH [(size_t)BNROWS*Dv];
__device__ __align__(16) __half g_XL [(size_t)BNROWS*Dv];
__device__ __align__(16) __half g_WT [4][1024*1024];       // W^T single fp16
__device__ __align__(16) __half g_QH [(size_t)BNROWS*Dv];
__device__ __align__(16) __half g_QLo[(size_t)BNROWS*Dv];
__device__ __align__(16) __half g_KTH[(size_t)Bv*Dv*Nv];
__device__ __align__(16) __half g_KTL[(size_t)Bv*Dv*Nv];
__device__ __align__(16) __half g_VTH[(size_t)Bv*Dv*Nv];   // hi only (B operand)
__device__ __align__(16) __half g_KVT[(size_t)Bv*Dv*Dv];   // hi only (B operand)

// ------------------------------ helpers ------------------------------------
__device__ __forceinline__ uint32_t s2u(const void* p) {
    uint32_t a;
    asm("{ .reg .u64 t; cvta.to.shared.u64 t, %1; cvt.u32.u64 %0, t; }" : "=r"(a) : "l"(p));
    return a;
}
__device__ __forceinline__ void cpa16(uint32_t dst, const void* src) {
    asm volatile("cp.async.cg.shared.global [%0], [%1], 16;" :: "r"(dst), "l"(src));
}
#define CPC() asm volatile("cp.async.commit_group;" ::: "memory")

__device__ __forceinline__ void ldsm4(uint32_t* r, uint32_t addr) {
    asm volatile("ldmatrix.sync.aligned.m8n8.x4.shared.b16 {%0,%1,%2,%3}, [%4];"
                 : "=r"(r[0]), "=r"(r[1]), "=r"(r[2]), "=r"(r[3]) : "r"(addr));
}
__device__ __forceinline__ void mmaf16(float* c, const uint32_t* a, const uint32_t* b) {
    asm volatile(
        "mma.sync.aligned.m16n8k16.row.col.f32.f16.f16.f32 "
        "{%0,%1,%2,%3}, {%4,%5,%6,%7}, {%8,%9}, {%0,%1,%2,%3};"
        : "+f"(c[0]), "+f"(c[1]), "+f"(c[2]), "+f"(c[3])
        : "r"(a[0]), "r"(a[1]), "r"(a[2]), "r"(a[3]), "r"(b[0]), "r"(b[1]));
}

__device__ __forceinline__ uint32_t pack_hl(float f) {
    __half h = __float2half_rn(f);
    __half l = __float2half_rn(f - __half2float(h));
    return ((uint32_t)__half_as_ushort(h) << 16) | __half_as_ushort(l);
}
__device__ __forceinline__ void split2pack(float f0, float f1, uint32_t& wh, uint32_t& wl) {
    __half h0 = __float2half_rn(f0);
    __half h1 = __float2half_rn(f1);
    __half l0 = __float2half_rn(f0 - __half2float(h0));
    __half l1 = __float2half_rn(f1 - __half2float(h1));
    wh = ((uint32_t)__half_as_ushort(h1) << 16) | __half_as_ushort(h0);
    wl = ((uint32_t)__half_as_ushort(l1) << 16) | __half_as_ushort(l0);
}

// Split-transpose epilogue: 128x128 C tile -> OH (and OL if non-null),
// output rows = bn+d (length ldo), cols = bm..
__device__ __forceinline__ void epi_splitT(
    const float (&acc)[4][4][4], char* sm,
    int wm, int wn, int lane, int tid,
    __half* __restrict__ OH, __half* __restrict__ OL,
    size_t base, int ldo)
{
    __syncthreads();
    uint32_t* s32 = (uint32_t*)sm;
#pragma unroll
    for (int mi = 0; mi < 4; mi++) {
        int r = wm + mi * 16 + (lane >> 2);
#pragma unroll
        for (int ni = 0; ni < 4; ni++) {
            int c = wn + ni * 8 + (lane & 3) * 2;
            s32[r * 133 + c]           = pack_hl(acc[mi][ni][0]);
            s32[r * 133 + c + 1]       = pack_hl(acc[mi][ni][1]);
            s32[(r + 8) * 133 + c]     = pack_hl(acc[mi][ni][2]);
            s32[(r + 8) * 133 + c + 1] = pack_hl(acc[mi][ni][3]);
        }
    }
    __syncthreads();
    int d = tid >> 1, nb = (tid & 1) * 64;
    __half* rh = OH + base + (size_t)d * ldo + nb;
#pragma unroll
    for (int j = 0; j < 8; j++) {
        alignas(16) __half hb[8], lb[8];
#pragma unroll
        for (int i = 0; i < 8; i++) {
            uint32_t w = s32[(nb + j * 8 + i) * 133 + d];
            hb[i] = __ushort_as_half((unsigned short)(w >> 16));
            lb[i] = __ushort_as_half((unsigned short)(w & 0xFFFFu));
        }
        *(uint4*)(rh + j * 8) = *(const uint4*)hb;
        if (OL) {
            __half* rl = OL + base + (size_t)d * ldo + nb;
            *(uint4*)(rl + j * 8) = *(const uint4*)lb;
        }
    }
}

// --------------------- single-B 2-pass GEMM --------------------------------
// C = (Ah+Al)[M,K] @ (B[N,K])^T. MODE 0: fp32 straight; MODE 1: splitT hi-only.
template<int MODE>
__global__ __launch_bounds__(GT, 1)
void gemm2(const __half* __restrict__ Ahg, const __half* __restrict__ Alg,
           const __half* __restrict__ Bg,
           float* __restrict__ Cf, __half* __restrict__ OH,
           int M, int N, int Kg, long sA, long sB, long sO)
{
    extern __shared__ char sm[];
    const uint32_t smu = s2u(sm);
    const int tid = threadIdx.x, lane = tid & 31, wid = tid >> 5;
    const int bm = blockIdx.y * 128, bn = blockIdx.x * 128;
    const int wm = (wid & 1) * 64, wn = (wid >> 1) * 32;

    const __half* Ah = Ahg + (size_t)blockIdx.z * sA;
    const __half* Al = Alg + (size_t)blockIdx.z * sA;
    const __half* Bp = Bg  + (size_t)blockIdx.z * sB;

    const int rr = tid >> 2, cg = tid & 3;
    const uint32_t so0 = SWZ64((uint32_t)(rr * 64 + cg * 16));
    const uint32_t so1 = SWZ64((uint32_t)((rr + 64) * 64 + cg * 16));
    const __half* gAh = Ah + (size_t)(bm + rr) * Kg + cg * 8;
    const __half* gAl = Al + (size_t)(bm + rr) * Kg + cg * 8;
    const __half* gB  = Bp + (size_t)(bn + rr) * Kg + cg * 8;
    const size_t rstep = (size_t)64 * Kg;

    uint32_t aoff[2][4], boff[2][2];
    {
        uint32_t arow = (uint32_t)(wm + (lane & 15));
        uint32_t acol = (uint32_t)((lane >> 4) * 16);
        uint32_t brow = (uint32_t)(wn + ((lane >> 4) << 3) + (lane & 7));
        uint32_t bcol = (uint32_t)(((lane >> 3) & 1) * 16);
#pragma unroll
        for (int ks = 0; ks < 2; ks++) {
#pragma unroll
            for (int mi = 0; mi < 4; mi++)
                aoff[ks][mi] = SWZ64((arow + mi * 16) * 64 + ks * 32 + acol);
#pragma unroll
            for (int g = 0; g < 2; g++)
                boff[ks][g] = SWZ64((brow + g * 16) * 64 + ks * 32 + bcol);
        }
    }

    float acc[4][4][4];
#pragma unroll
    for (int mi = 0; mi < 4; mi++)
#pragma unroll
        for (int ni = 0; ni < 4; ni++)
#pragma unroll
            for (int j = 0; j < 4; j++) acc[mi][ni][j] = 0.0f;

    const int nch = Kg / 32;
    auto load_stage = [&](int c) {
        const uint32_t st = smu + (uint32_t)(c & (NST - 1)) * STG1;
        const int k0 = c * 32;
        cpa16(st + so0,          gAh + k0);
        cpa16(st + so1,          gAh + k0 + rstep);
        cpa16(st + ASZ + so0,    gAl + k0);
        cpa16(st + ASZ + so1,    gAl + k0 + rstep);
        cpa16(st + 2*ASZ + so0,  gB + k0);
        cpa16(st + 2*ASZ + so1,  gB + k0 + rstep);
        CPC();
    };

    load_stage(0); load_stage(1); load_stage(2);

    for (int c = 0; c < nch; ++c) {
        asm volatile("cp.async.wait_group 2;" ::: "memory");
        __syncthreads();
        if (c + 3 < nch) load_stage(c + 3);

        const uint32_t st = smu + (uint32_t)(c & (NST - 1)) * STG1;
#pragma unroll
        for (int ks = 0; ks < 2; ks++) {
            uint32_t ah[4][4], al[4][4];
#pragma unroll
            for (int mi = 0; mi < 4; mi++) {
                ldsm4(ah[mi], st + aoff[ks][mi]);
                ldsm4(al[mi], st + ASZ + aoff[ks][mi]);
            }
#pragma unroll
            for (int g = 0; g < 2; g++) {
                uint32_t tb[4];
                ldsm4(tb, st + 2*ASZ + boff[ks][g]);
#pragma unroll
                for (int mi = 0; mi < 4; mi++) {
                    mmaf16(acc[mi][2*g],   ah[mi], tb);
                    mmaf16(acc[mi][2*g],   al[mi], tb);
                    mmaf16(acc[mi][2*g+1], ah[mi], tb + 2);
                    mmaf16(acc[mi][2*g+1], al[mi], tb + 2);
                }
            }
        }
    }

    if (MODE == 0) {
        float* Cb = Cf + (size_t)blockIdx.z * sO;
#pragma unroll
        for (int mi = 0; mi < 4; mi++) {
            int rA = bm + wm + mi * 16 + (lane >> 2);
#pragma unroll
            for (int ni = 0; ni < 4; ni++) {
                int col = bn + wn + ni * 8 + (lane & 3) * 2;
                *(float2*)(Cb + (size_t)rA * N + col)       = make_float2(acc[mi][ni][0], acc[mi][ni][1]);
                *(float2*)(Cb + (size_t)(rA + 8) * N + col) = make_float2(acc[mi][ni][2], acc[mi][ni][3]);
            }
        }
    } else {
        size_t base = (size_t)blockIdx.z * sO + (size_t)bn * M + bm;
        epi_splitT(acc, sm, wm, wn, lane, tid, OH + 0, nullptr, base, M);
    }
}

// --------------------- dual-B 2-pass GEMM (projections) ---------------------
// C1 = A@B1^T, C2 = A@B2^T. GATE=1: split(C1*C2) straight [M,N] hi/lo.
// GATE=0: C1 -> splitT hi/lo (k^T); C2 -> splitT hi only (v^T).
template<int GATE>
__global__ __launch_bounds__(GT, 1)
void gemm2_dual(const __half* __restrict__ Ah, const __half* __restrict__ Al,
                const __half* __restrict__ B1, const __half* __restrict__ B2,
                __half* __restrict__ O1H, __half* __restrict__ O1L,
                __half* __restrict__ O2H,
                int N, int Kg)
{
    extern __shared__ char sm[];
    const uint32_t smu = s2u(sm);
    const int tid = threadIdx.x, lane = tid & 31, wid = tid >> 5;
    const int bm = blockIdx.y * 128, bn = blockIdx.x * 128;
    const int wm = (wid & 1) * 64, wn = (wid >> 1) * 32;

    const int rr = tid >> 2, cg = tid & 3;
    const uint32_t so0 = SWZ64((uint32_t)(rr * 64 + cg * 16));
    const uint32_t so1 = SWZ64((uint32_t)((rr + 64) * 64 + cg * 16));
    const __half* gAh = Ah + (size_t)(bm + rr) * Kg + cg * 8;
    const __half* gAl = Al + (size_t)(bm + rr) * Kg + cg * 8;
    const __half* g1  = B1 + (size_t)(bn + rr) * Kg + cg * 8;
    const __half* g2  = B2 + (size_t)(bn + rr) * Kg + cg * 8;
    const size_t rstep = (size_t)64 * Kg;

    uint32_t aoff[2][4], boff[2][2];
    {
        uint32_t arow = (uint32_t)(wm + (lane & 15));
        uint32_t acol = (uint32_t)((lane >> 4) * 16);
        uint32_t brow = (uint32_t)(wn + ((lane >> 4) << 3) + (lane & 7));
        uint32_t bcol = (uint32_t)(((lane >> 3) & 1) * 16);
#pragma unroll
        for (int ks = 0; ks < 2; ks++) {
#pragma unroll
            for (int mi = 0; mi < 4; mi++)
                aoff[ks][mi] = SWZ64((arow + mi * 16) * 64 + ks * 32 + acol);
#pragma unroll
            for (int g = 0; g < 2; g++)
                boff[ks][g] = SWZ64((brow + g * 16) * 64 + ks * 32 + bcol);
        }
    }

    float a1[4][4][4], a2[4][4][4];
#pragma unroll
    for (int mi = 0; mi < 4; mi++)
#pragma unroll
        for (int ni = 0; ni < 4; ni++)
#pragma unroll
            for (int j = 0; j < 4; j++) { a1[mi][ni][j] = 0.0f; a2[mi][ni][j] = 0.0f; }

    const int nch = Kg / 32;
    auto load_stage = [&](int c) {
        const uint32_t st = smu + (uint32_t)(c & (NST - 1)) * STG2;
        const int k0 = c * 32;
        cpa16(st + so0,          gAh + k0);
        cpa16(st + so1,          gAh + k0 + rstep);
        cpa16(st + ASZ + so0,    gAl + k0);
        cpa16(st + ASZ + so1,    gAl + k0 + rstep);
        cpa16(st + 2*ASZ + so0,  g1 + k0);
        cpa16(st + 2*ASZ + so1,  g1 + k0 + rstep);
        cpa16(st + 3*ASZ + so0,  g2 + k0);
        cpa16(st + 3*ASZ + so1,  g2 + k0 + rstep);
        CPC();
    };

    load_stage(0); load_stage(1); load_stage(2);

    for (int c = 0; c < nch; ++c) {
        asm volatile("cp.async.wait_group 2;" ::: "memory");
        __syncthreads();
        if (c + 3 < nch) load_stage(c + 3);

        const uint32_t st = smu + (uint32_t)(c & (NST - 1)) * STG2;
#pragma unroll
        for (int ks = 0; ks < 2; ks++) {
            uint32_t ah[4][4], al[4][4];
#pragma unroll
            for (int mi = 0; mi < 4; mi++) {
                ldsm4(ah[mi], st + aoff[ks][mi]);
                ldsm4(al[mi], st + ASZ + aoff[ks][mi]);
            }
#pragma unroll
            for (int g = 0; g < 2; g++) {
                uint32_t t1[4], t2[4];
                ldsm4(t1, st + 2*ASZ + boff[ks][g]);
                ldsm4(t2, st + 3*ASZ + boff[ks][g]);
#pragma unroll
                for (int mi = 0; mi < 4; mi++) {
                    mmaf16(a1[mi][2*g],   ah[mi], t1);
                    mmaf16(a1[mi][2*g],   al[mi], t1);
                    mmaf16(a1[mi][2*g+1], ah[mi], t1 + 2);
                    mmaf16(a1[mi][2*g+1], al[mi], t1 + 2);
                    mmaf16(a2[mi][2*g],   ah[mi], t2);
                    mmaf16(a2[mi][2*g],   al[mi], t2);
                    mmaf16(a2[mi][2*g+1], ah[mi], t2 + 2);
                    mmaf16(a2[mi][2*g+1], al[mi], t2 + 2);
                }
            }
        }
    }

    if (GATE == 1) {
#pragma unroll
        for (int mi = 0; mi < 4; mi++) {
            int r = bm + wm + mi * 16 + (lane >> 2);
#pragma unroll
            for (int ni = 0; ni < 4; ni++) {
                int c = bn + wn + ni * 8 + (lane & 3) * 2;
                uint32_t wh, wl;
                split2pack(a1[mi][ni][0]*a2[mi][ni][0], a1[mi][ni][1]*a2[mi][ni][1], wh, wl);
                *(uint32_t*)(O1H + (size_t)r * N + c) = wh;
                *(uint32_t*)(O1L + (size_t)r * N + c) = wl;
                split2pack(a1[mi][ni][2]*a2[mi][ni][2], a1[mi][ni][3]*a2[mi][ni][3], wh, wl);
                *(uint32_t*)(O1H + (size_t)(r + 8) * N + c) = wh;
                *(uint32_t*)(O1L + (size_t)(r + 8) * N + c) = wl;
            }
        }
    } else {
        size_t batch = (size_t)(bm >> 12);
        size_t base = batch * (size_t)Dv * Nv + (size_t)bn * Nv + (bm & 4095);
        epi_splitT(a1, sm, wm, wn, lane, tid, O1H, O1L, base, Nv);
        epi_splitT(a2, sm, wm, wn, lane, tid, O2H, nullptr, base, Nv);
    }
}

// --------------------------- conversion kernels ----------------------------
__global__ void split_x(const float* __restrict__ in,
                        __half* __restrict__ oh, __half* __restrict__ ol) {
    size_t i = (size_t)blockIdx.x * blockDim.x + threadIdx.x;
    float4 f = ((const float4*)in)[i];
    __half h0 = __float2half_rn(f.x), h1 = __float2half_rn(f.y);
    __half h2 = __float2half_rn(f.z), h3 = __float2half_rn(f.w);
    __half l0 = __float2half_rn(f.x - __half2float(h0));
    __half l1 = __float2half_rn(f.y - __half2float(h1));
    __half l2 = __float2half_rn(f.z - __half2float(h2));
    __half l3 = __float2half_rn(f.w - __half2float(h3));
    ((__half2*)oh)[i*2]   = __halves2half2(h0, h1);
    ((__half2*)oh)[i*2+1] = __halves2half2(h2, h3);
    ((__half2*)ol)[i*2]   = __halves2half2(l0, l1);
    ((__half2*)ol)[i*2+1] = __halves2half2(l2, l3);
}

// w[d][e] fp32 -> w^T[e][d] single fp16, z selects weight
__global__ void conv_wT(const float* w0, const float* w1, const float* w2, const float* w3,
                        __half* __restrict__ O) {
    const float* in = (blockIdx.z == 0) ? w0 : (blockIdx.z == 1) ? w1
                     : (blockIdx.z == 2) ? w2 : w3;
    __half* o = O + (size_t)blockIdx.z * Dv * Dv;
    __shared__ float t[32][33];
    int c0 = blockIdx.x * 32, r0 = blockIdx.y * 32;
    int tx = threadIdx.x, ty = threadIdx.y;
#pragma unroll
    for (int i = 0; i < 4; i++)
        t[ty + i*8][tx] = in[(size_t)(r0 + ty + i*8) * Dv + c0 + tx];
    __syncthreads();
#pragma unroll
    for (int i = 0; i < 4; i++) {
        int oc = c0 + ty + i*8, od = r0 + tx;
        o[(size_t)oc * Dv + od] = __float2half_rn(t[tx][ty + i*8]);
    }
}

// ------------------------------- launch ------------------------------------
extern "C" void kernel_launch(void* const* d_in, const int* in_sizes, int n_in,
                              void* d_out, int out_size) {
    const float* x   = (const float*)d_in[0];
    const float* w[4] = { (const float*)d_in[1], (const float*)d_in[2],
                          (const float*)d_in[3], (const float*)d_in[4] };
    float* out = (float*)d_out;

    __half *XH,*XL,*WT,*QH,*QLo,*KTH,*KTL,*VTH,*KVT;
    cudaGetSymbolAddress((void**)&XH,  g_XH);   cudaGetSymbolAddress((void**)&XL,  g_XL);
    cudaGetSymbolAddress((void**)&WT,  g_WT);
    cudaGetSymbolAddress((void**)&QH,  g_QH);   cudaGetSymbolAddress((void**)&QLo, g_QLo);
    cudaGetSymbolAddress((void**)&KTH, g_KTH);  cudaGetSymbolAddress((void**)&KTL, g_KTL);
    cudaGetSymbolAddress((void**)&VTH, g_VTH);  cudaGetSymbolAddress((void**)&KVT, g_KVT);

    cudaFuncSetAttribute(gemm2<0>,      cudaFuncAttributeMaxDynamicSharedMemorySize, SMEM1);
    cudaFuncSetAttribute(gemm2<1>,      cudaFuncAttributeMaxDynamicSharedMemorySize, SMEM1);
    cudaFuncSetAttribute(gemm2_dual<0>, cudaFuncAttributeMaxDynamicSharedMemorySize, SMEM2);
    cudaFuncSetAttribute(gemm2_dual<1>, cudaFuncAttributeMaxDynamicSharedMemorySize, SMEM2);

    const size_t DDe = (size_t)Dv * Dv;
    const size_t PNe = (size_t)BNROWS * Dv;
    dim3 tb32(32, 8);

    // 1) conversions
    split_x<<<(unsigned)(PNe/4/256), 256>>>(x, XH, XL);
    conv_wT<<<dim3(Dv/32, Dv/32, 4), tb32>>>(w[0], w[1], w[2], w[3], WT);

    // 2) q = (x@Wql)*(x@Wqr) -> split straight hi/lo
    gemm2_dual<1><<<dim3(Dv/128, BNROWS/128), GT, SMEM2>>>(
        XH, XL, WT + 0*DDe, WT + 1*DDe, QH, QLo, nullptr, Dv, Dv);

    // 3) k, v -> k^T split hi/lo; v^T hi only (per-batch [Dv][Nv])
    gemm2_dual<0><<<dim3(Dv/128, BNROWS/128), GT, SMEM2>>>(
        XH, XL, WT + 2*DDe, WT + 3*DDe, KTH, KTL, VTH, Dv, Dv);

    // 4) kv[b] = k^T@v -> kv^T hi only [Dv][Dv]
    gemm2<1><<<dim3(Dv/128, Dv/128, Bv), GT, SMEM1>>>(
        KTH, KTL, VTH, nullptr, KVT,
        Dv, Dv, Nv, (long)Dv*Nv, (long)Dv*Nv, (long)DDe);

    // 5) out[b] = q@kv -> fp32
    gemm2<0><<<dim3(Dv/128, Nv/128, Bv), GT, SMEM1>>>(
        QH, QLo, KVT, out, nullptr,
        Nv, Dv, Dv, (long)Nv*Dv, (long)DDe, (long)Nv*Dv);
}

// round 9
// speedup vs baseline: 4.0945x; 1.3106x over previous
#include <cuda_runtime.h>
#include <cuda_fp16.h>
#include <cstdint>

// LinearAttention B=4, N=4096, D=1024 fp32
// R9: 1-pass fp16 projections (x, W single fp16); kv/out stay 2-pass
//     (A split hi/lo exact, B single fp16). Fused gate/splitT epilogues.

#define Bv 4
#define Nv 4096
#define Dv 1024
#define BNROWS (Bv*Nv)            // 16384

#define GT 256                    // 8 warps
#define ASZ 8192                  // 128 rows x 64B operand tile

#define STG1 (3*ASZ)              // single-B 2-pass stage: Ah,Al,B
#define NST 4
#define SMEM1 (NST*STG1)          // 98304
#define STG2 (3*ASZ)              // dual-B 1-pass stage: A,B1,B2
#define SMEM2 (NST*STG2)          // 98304

#define SWZ64(x) ((x) ^ (((x) >> 3) & 0x30))

// ------------------------------ scratch -----------------------------------
__device__ __align__(16) __half g_X  [(size_t)BNROWS*Dv];  // x single fp16
__device__ __align__(16) __half g_WT [4][1024*1024];       // W^T single fp16
__device__ __align__(16) __half g_QH [(size_t)BNROWS*Dv];
__device__ __align__(16) __half g_QLo[(size_t)BNROWS*Dv];
__device__ __align__(16) __half g_KTH[(size_t)Bv*Dv*Nv];
__device__ __align__(16) __half g_KTL[(size_t)Bv*Dv*Nv];
__device__ __align__(16) __half g_VTH[(size_t)Bv*Dv*Nv];   // hi only (B operand)
__device__ __align__(16) __half g_KVT[(size_t)Bv*Dv*Dv];   // hi only (B operand)

// ------------------------------ helpers ------------------------------------
__device__ __forceinline__ uint32_t s2u(const void* p) {
    uint32_t a;
    asm("{ .reg .u64 t; cvta.to.shared.u64 t, %1; cvt.u32.u64 %0, t; }" : "=r"(a) : "l"(p));
    return a;
}
__device__ __forceinline__ void cpa16(uint32_t dst, const void* src) {
    asm volatile("cp.async.cg.shared.global [%0], [%1], 16;" :: "r"(dst), "l"(src));
}
#define CPC() asm volatile("cp.async.commit_group;" ::: "memory")

__device__ __forceinline__ void ldsm4(uint32_t* r, uint32_t addr) {
    asm volatile("ldmatrix.sync.aligned.m8n8.x4.shared.b16 {%0,%1,%2,%3}, [%4];"
                 : "=r"(r[0]), "=r"(r[1]), "=r"(r[2]), "=r"(r[3]) : "r"(addr));
}
__device__ __forceinline__ void mmaf16(float* c, const uint32_t* a, const uint32_t* b) {
    asm volatile(
        "mma.sync.aligned.m16n8k16.row.col.f32.f16.f16.f32 "
        "{%0,%1,%2,%3}, {%4,%5,%6,%7}, {%8,%9}, {%0,%1,%2,%3};"
        : "+f"(c[0]), "+f"(c[1]), "+f"(c[2]), "+f"(c[3])
        : "r"(a[0]), "r"(a[1]), "r"(a[2]), "r"(a[3]), "r"(b[0]), "r"(b[1]));
}

__device__ __forceinline__ uint32_t pack_hl(float f) {
    __half h = __float2half_rn(f);
    __half l = __float2half_rn(f - __half2float(h));
    return ((uint32_t)__half_as_ushort(h) << 16) | __half_as_ushort(l);
}
__device__ __forceinline__ void split2pack(float f0, float f1, uint32_t& wh, uint32_t& wl) {
    __half h0 = __float2half_rn(f0);
    __half h1 = __float2half_rn(f1);
    __half l0 = __float2half_rn(f0 - __half2float(h0));
    __half l1 = __float2half_rn(f1 - __half2float(h1));
    wh = ((uint32_t)__half_as_ushort(h1) << 16) | __half_as_ushort(h0);
    wl = ((uint32_t)__half_as_ushort(l1) << 16) | __half_as_ushort(l0);
}

// Split-transpose epilogue: 128x128 C tile -> OH (and OL if non-null),
// output rows = bn+d (length ldo), cols = bm..
__device__ __forceinline__ void epi_splitT(
    const float (&acc)[4][4][4], char* sm,
    int wm, int wn, int lane, int tid,
    __half* __restrict__ OH, __half* __restrict__ OL,
    size_t base, int ldo)
{
    __syncthreads();
    uint32_t* s32 = (uint32_t*)sm;
#pragma unroll
    for (int mi = 0; mi < 4; mi++) {
        int r = wm + mi * 16 + (lane >> 2);
#pragma unroll
        for (int ni = 0; ni < 4; ni++) {
            int c = wn + ni * 8 + (lane & 3) * 2;
            s32[r * 133 + c]           = pack_hl(acc[mi][ni][0]);
            s32[r * 133 + c + 1]       = pack_hl(acc[mi][ni][1]);
            s32[(r + 8) * 133 + c]     = pack_hl(acc[mi][ni][2]);
            s32[(r + 8) * 133 + c + 1] = pack_hl(acc[mi][ni][3]);
        }
    }
    __syncthreads();
    int d = tid >> 1, nb = (tid & 1) * 64;
    __half* rh = OH + base + (size_t)d * ldo + nb;
#pragma unroll
    for (int j = 0; j < 8; j++) {
        alignas(16) __half hb[8], lb[8];
#pragma unroll
        for (int i = 0; i < 8; i++) {
            uint32_t w = s32[(nb + j * 8 + i) * 133 + d];
            hb[i] = __ushort_as_half((unsigned short)(w >> 16));
            lb[i] = __ushort_as_half((unsigned short)(w & 0xFFFFu));
        }
        *(uint4*)(rh + j * 8) = *(const uint4*)hb;
        if (OL) {
            __half* rl = OL + base + (size_t)d * ldo + nb;
            *(uint4*)(rl + j * 8) = *(const uint4*)lb;
        }
    }
}

// --------------------- single-B 2-pass GEMM (kv / out) ----------------------
// C = (Ah+Al)[M,K] @ (B[N,K])^T. MODE 0: fp32 straight; MODE 1: splitT hi-only.
template<int MODE>
__global__ __launch_bounds__(GT, 1)
void gemm2(const __half* __restrict__ Ahg, const __half* __restrict__ Alg,
           const __half* __restrict__ Bg,
           float* __restrict__ Cf, __half* __restrict__ OH,
           int M, int N, int Kg, long sA, long sB, long sO)
{
    extern __shared__ char sm[];
    const uint32_t smu = s2u(sm);
    const int tid = threadIdx.x, lane = tid & 31, wid = tid >> 5;
    const int bm = blockIdx.y * 128, bn = blockIdx.x * 128;
    const int wm = (wid & 1) * 64, wn = (wid >> 1) * 32;

    const __half* Ah = Ahg + (size_t)blockIdx.z * sA;
    const __half* Al = Alg + (size_t)blockIdx.z * sA;
    const __half* Bp = Bg  + (size_t)blockIdx.z * sB;

    const int rr = tid >> 2, cg = tid & 3;
    const uint32_t so0 = SWZ64((uint32_t)(rr * 64 + cg * 16));
    const uint32_t so1 = SWZ64((uint32_t)((rr + 64) * 64 + cg * 16));
    const __half* gAh = Ah + (size_t)(bm + rr) * Kg + cg * 8;
    const __half* gAl = Al + (size_t)(bm + rr) * Kg + cg * 8;
    const __half* gB  = Bp + (size_t)(bn + rr) * Kg + cg * 8;
    const size_t rstep = (size_t)64 * Kg;

    uint32_t aoff[2][4], boff[2][2];
    {
        uint32_t arow = (uint32_t)(wm + (lane & 15));
        uint32_t acol = (uint32_t)((lane >> 4) * 16);
        uint32_t brow = (uint32_t)(wn + ((lane >> 4) << 3) + (lane & 7));
        uint32_t bcol = (uint32_t)(((lane >> 3) & 1) * 16);
#pragma unroll
        for (int ks = 0; ks < 2; ks++) {
#pragma unroll
            for (int mi = 0; mi < 4; mi++)
                aoff[ks][mi] = SWZ64((arow + mi * 16) * 64 + ks * 32 + acol);
#pragma unroll
            for (int g = 0; g < 2; g++)
                boff[ks][g] = SWZ64((brow + g * 16) * 64 + ks * 32 + bcol);
        }
    }

    float acc[4][4][4];
#pragma unroll
    for (int mi = 0; mi < 4; mi++)
#pragma unroll
        for (int ni = 0; ni < 4; ni++)
#pragma unroll
            for (int j = 0; j < 4; j++) acc[mi][ni][j] = 0.0f;

    const int nch = Kg / 32;
    auto load_stage = [&](int c) {
        const uint32_t st = smu + (uint32_t)(c & (NST - 1)) * STG1;
        const int k0 = c * 32;
        cpa16(st + so0,          gAh + k0);
        cpa16(st + so1,          gAh + k0 + rstep);
        cpa16(st + ASZ + so0,    gAl + k0);
        cpa16(st + ASZ + so1,    gAl + k0 + rstep);
        cpa16(st + 2*ASZ + so0,  gB + k0);
        cpa16(st + 2*ASZ + so1,  gB + k0 + rstep);
        CPC();
    };

    load_stage(0); load_stage(1); load_stage(2);

    for (int c = 0; c < nch; ++c) {
        asm volatile("cp.async.wait_group 2;" ::: "memory");
        __syncthreads();
        if (c + 3 < nch) load_stage(c + 3);

        const uint32_t st = smu + (uint32_t)(c & (NST - 1)) * STG1;
#pragma unroll
        for (int ks = 0; ks < 2; ks++) {
            uint32_t ah[4][4], al[4][4];
#pragma unroll
            for (int mi = 0; mi < 4; mi++) {
                ldsm4(ah[mi], st + aoff[ks][mi]);
                ldsm4(al[mi], st + ASZ + aoff[ks][mi]);
            }
#pragma unroll
            for (int g = 0; g < 2; g++) {
                uint32_t tb[4];
                ldsm4(tb, st + 2*ASZ + boff[ks][g]);
#pragma unroll
                for (int mi = 0; mi < 4; mi++) {
                    mmaf16(acc[mi][2*g],   ah[mi], tb);
                    mmaf16(acc[mi][2*g],   al[mi], tb);
                    mmaf16(acc[mi][2*g+1], ah[mi], tb + 2);
                    mmaf16(acc[mi][2*g+1], al[mi], tb + 2);
                }
            }
        }
    }

    if (MODE == 0) {
        float* Cb = Cf + (size_t)blockIdx.z * sO;
#pragma unroll
        for (int mi = 0; mi < 4; mi++) {
            int rA = bm + wm + mi * 16 + (lane >> 2);
#pragma unroll
            for (int ni = 0; ni < 4; ni++) {
                int col = bn + wn + ni * 8 + (lane & 3) * 2;
                *(float2*)(Cb + (size_t)rA * N + col)       = make_float2(acc[mi][ni][0], acc[mi][ni][1]);
                *(float2*)(Cb + (size_t)(rA + 8) * N + col) = make_float2(acc[mi][ni][2], acc[mi][ni][3]);
            }
        }
    } else {
        size_t base = (size_t)blockIdx.z * sO + (size_t)bn * M + bm;
        epi_splitT(acc, sm, wm, wn, lane, tid, OH, nullptr, base, M);
    }
}

// --------------- dual-B 1-pass GEMM (projections, fp16 single) --------------
// C1 = A@B1^T, C2 = A@B2^T. GATE=1: split(C1*C2) straight [M,N] hi/lo.
// GATE=0: C1 -> splitT hi/lo (k^T); C2 -> splitT hi only (v^T).
template<int GATE>
__global__ __launch_bounds__(GT, 1)
void gemm1_dual(const __half* __restrict__ Ag,
                const __half* __restrict__ B1, const __half* __restrict__ B2,
                __half* __restrict__ O1H, __half* __restrict__ O1L,
                __half* __restrict__ O2H,
                int N, int Kg)
{
    extern __shared__ char sm[];
    const uint32_t smu = s2u(sm);
    const int tid = threadIdx.x, lane = tid & 31, wid = tid >> 5;
    const int bm = blockIdx.y * 128, bn = blockIdx.x * 128;
    const int wm = (wid & 1) * 64, wn = (wid >> 1) * 32;

    const int rr = tid >> 2, cg = tid & 3;
    const uint32_t so0 = SWZ64((uint32_t)(rr * 64 + cg * 16));
    const uint32_t so1 = SWZ64((uint32_t)((rr + 64) * 64 + cg * 16));
    const __half* gA = Ag + (size_t)(bm + rr) * Kg + cg * 8;
    const __half* g1 = B1 + (size_t)(bn + rr) * Kg + cg * 8;
    const __half* g2 = B2 + (size_t)(bn + rr) * Kg + cg * 8;
    const size_t rstep = (size_t)64 * Kg;

    uint32_t aoff[2][4], boff[2][2];
    {
        uint32_t arow = (uint32_t)(wm + (lane & 15));
        uint32_t acol = (uint32_t)((lane >> 4) * 16);
        uint32_t brow = (uint32_t)(wn + ((lane >> 4) << 3) + (lane & 7));
        uint32_t bcol = (uint32_t)(((lane >> 3) & 1) * 16);
#pragma unroll
        for (int ks = 0; ks < 2; ks++) {
#pragma unroll
            for (int mi = 0; mi < 4; mi++)
                aoff[ks][mi] = SWZ64((arow + mi * 16) * 64 + ks * 32 + acol);
#pragma unroll
            for (int g = 0; g < 2; g++)
                boff[ks][g] = SWZ64((brow + g * 16) * 64 + ks * 32 + bcol);
        }
    }

    float a1[4][4][4], a2[4][4][4];
#pragma unroll
    for (int mi = 0; mi < 4; mi++)
#pragma unroll
        for (int ni = 0; ni < 4; ni++)
#pragma unroll
            for (int j = 0; j < 4; j++) { a1[mi][ni][j] = 0.0f; a2[mi][ni][j] = 0.0f; }

    const int nch = Kg / 32;
    auto load_stage = [&](int c) {
        const uint32_t st = smu + (uint32_t)(c & (NST - 1)) * STG2;
        const int k0 = c * 32;
        cpa16(st + so0,          gA + k0);
        cpa16(st + so1,          gA + k0 + rstep);
        cpa16(st + ASZ + so0,    g1 + k0);
        cpa16(st + ASZ + so1,    g1 + k0 + rstep);
        cpa16(st + 2*ASZ + so0,  g2 + k0);
        cpa16(st + 2*ASZ + so1,  g2 + k0 + rstep);
        CPC();
    };

    load_stage(0); load_stage(1); load_stage(2);

    for (int c = 0; c < nch; ++c) {
        asm volatile("cp.async.wait_group 2;" ::: "memory");
        __syncthreads();
        if (c + 3 < nch) load_stage(c + 3);

        const uint32_t st = smu + (uint32_t)(c & (NST - 1)) * STG2;
#pragma unroll
        for (int ks = 0; ks < 2; ks++) {
            uint32_t ah[4][4];
#pragma unroll
            for (int mi = 0; mi < 4; mi++)
                ldsm4(ah[mi], st + aoff[ks][mi]);
#pragma unroll
            for (int g = 0; g < 2; g++) {
                uint32_t t1[4], t2[4];
                ldsm4(t1, st + ASZ + boff[ks][g]);
                ldsm4(t2, st + 2*ASZ + boff[ks][g]);
#pragma unroll
                for (int mi = 0; mi < 4; mi++) {
                    mmaf16(a1[mi][2*g],   ah[mi], t1);
                    mmaf16(a1[mi][2*g+1], ah[mi], t1 + 2);
                    mmaf16(a2[mi][2*g],   ah[mi], t2);
                    mmaf16(a2[mi][2*g+1], ah[mi], t2 + 2);
                }
            }
        }
    }

    if (GATE == 1) {
#pragma unroll
        for (int mi = 0; mi < 4; mi++) {
            int r = bm + wm + mi * 16 + (lane >> 2);
#pragma unroll
            for (int ni = 0; ni < 4; ni++) {
                int c = bn + wn + ni * 8 + (lane & 3) * 2;
                uint32_t wh, wl;
                split2pack(a1[mi][ni][0]*a2[mi][ni][0], a1[mi][ni][1]*a2[mi][ni][1], wh, wl);
                *(uint32_t*)(O1H + (size_t)r * N + c) = wh;
                *(uint32_t*)(O1L + (size_t)r * N + c) = wl;
                split2pack(a1[mi][ni][2]*a2[mi][ni][2], a1[mi][ni][3]*a2[mi][ni][3], wh, wl);
                *(uint32_t*)(O1H + (size_t)(r + 8) * N + c) = wh;
                *(uint32_t*)(O1L + (size_t)(r + 8) * N + c) = wl;
            }
        }
    } else {
        size_t batch = (size_t)(bm >> 12);
        size_t base = batch * (size_t)Dv * Nv + (size_t)bn * Nv + (bm & 4095);
        epi_splitT(a1, sm, wm, wn, lane, tid, O1H, O1L, base, Nv);
        epi_splitT(a2, sm, wm, wn, lane, tid, O2H, nullptr, base, Nv);
    }
}

// --------------------------- conversion kernels ----------------------------
__global__ void conv_x(const float* __restrict__ in, __half* __restrict__ o) {
    size_t i = (size_t)blockIdx.x * blockDim.x + threadIdx.x;
    float4 f = ((const float4*)in)[i];
    ((__half2*)o)[i*2]   = __halves2half2(__float2half_rn(f.x), __float2half_rn(f.y));
    ((__half2*)o)[i*2+1] = __halves2half2(__float2half_rn(f.z), __float2half_rn(f.w));
}

// w[d][e] fp32 -> w^T[e][d] single fp16, z selects weight
__global__ void conv_wT(const float* w0, const float* w1, const float* w2, const float* w3,
                        __half* __restrict__ O) {
    const float* in = (blockIdx.z == 0) ? w0 : (blockIdx.z == 1) ? w1
                     : (blockIdx.z == 2) ? w2 : w3;
    __half* o = O + (size_t)blockIdx.z * Dv * Dv;
    __shared__ float t[32][33];
    int c0 = blockIdx.x * 32, r0 = blockIdx.y * 32;
    int tx = threadIdx.x, ty = threadIdx.y;
#pragma unroll
    for (int i = 0; i < 4; i++)
        t[ty + i*8][tx] = in[(size_t)(r0 + ty + i*8) * Dv + c0 + tx];
    __syncthreads();
#pragma unroll
    for (int i = 0; i < 4; i++) {
        int oc = c0 + ty + i*8, od = r0 + tx;
        o[(size_t)oc * Dv + od] = __float2half_rn(t[tx][ty + i*8]);
    }
}

// ------------------------------- launch ------------------------------------
extern "C" void kernel_launch(void* const* d_in, const int* in_sizes, int n_in,
                              void* d_out, int out_size) {
    const float* x   = (const float*)d_in[0];
    const float* w[4] = { (const float*)d_in[1], (const float*)d_in[2],
                          (const float*)d_in[3], (const float*)d_in[4] };
    float* out = (float*)d_out;

    __half *X,*WT,*QH,*QLo,*KTH,*KTL,*VTH,*KVT;
    cudaGetSymbolAddress((void**)&X,   g_X);
    cudaGetSymbolAddress((void**)&WT,  g_WT);
    cudaGetSymbolAddress((void**)&QH,  g_QH);   cudaGetSymbolAddress((void**)&QLo, g_QLo);
    cudaGetSymbolAddress((void**)&KTH, g_KTH);  cudaGetSymbolAddress((void**)&KTL, g_KTL);
    cudaGetSymbolAddress((void**)&VTH, g_VTH);  cudaGetSymbolAddress((void**)&KVT, g_KVT);

    cudaFuncSetAttribute(gemm2<0>,      cudaFuncAttributeMaxDynamicSharedMemorySize, SMEM1);
    cudaFuncSetAttribute(gemm2<1>,      cudaFuncAttributeMaxDynamicSharedMemorySize, SMEM1);
    cudaFuncSetAttribute(gemm1_dual<0>, cudaFuncAttributeMaxDynamicSharedMemorySize, SMEM2);
    cudaFuncSetAttribute(gemm1_dual<1>, cudaFuncAttributeMaxDynamicSharedMemorySize, SMEM2);

    const size_t DDe = (size_t)Dv * Dv;
    const size_t PNe = (size_t)BNROWS * Dv;
    dim3 tb32(32, 8);

    // 1) conversions (x, W^T single fp16)
    conv_x<<<(unsigned)(PNe/4/256), 256>>>(x, X);
    conv_wT<<<dim3(Dv/32, Dv/32, 4), tb32>>>(w[0], w[1], w[2], w[3], WT);

    // 2) q = (x@Wql)*(x@Wqr) -> split straight hi/lo (1-pass proj)
    gemm1_dual<1><<<dim3(Dv/128, BNROWS/128), GT, SMEM2>>>(
        X, WT + 0*DDe, WT + 1*DDe, QH, QLo, nullptr, Dv, Dv);

    // 3) k, v -> k^T split hi/lo; v^T hi only (1-pass proj)
    gemm1_dual<0><<<dim3(Dv/128, BNROWS/128), GT, SMEM2>>>(
        X, WT + 2*DDe, WT + 3*DDe, KTH, KTL, VTH, Dv, Dv);

    // 4) kv[b] = k^T@v -> kv^T hi only [Dv][Dv]   (2-pass, A=k^T hi/lo)
    gemm2<1><<<dim3(Dv/128, Dv/128, Bv), GT, SMEM1>>>(
        KTH, KTL, VTH, nullptr, KVT,
        Dv, Dv, Nv, (long)Dv*Nv, (long)Dv*Nv, (long)DDe);

    // 5) out[b] = q@kv -> fp32   (2-pass, A=q hi/lo)
    gemm2<0><<<dim3(Dv/128, Nv/128, Bv), GT, SMEM1>>>(
        QH, QLo, KVT, out, nullptr,
        Nv, Dv, Dv, (long)Nv*Dv, (long)DDe, (long)Nv*Dv);
}

// round 10
// speedup vs baseline: 4.5922x; 1.1215x over previous
#include <cuda_runtime.h>
#include <cuda_fp16.h>
#include <cstdint>

// LinearAttention B=4, N=4096, D=1024 fp32
// R10: 512-thread CTAs (16 warps, 32x32 warp tile) for occupancy;
//      1-pass fp16 projections AND kv (k^T hi-only); out stays 2-pass.

#define Bv 4
#define Nv 4096
#define Dv 1024
#define BNROWS (Bv*Nv)            // 16384

#define GT 512                    // 16 warps
#define ASZ 8192                  // 128 rows x 64B operand tile
#define NST 4

#define STGD (3*ASZ)              // dual 1-pass: A,B1,B2
#define SMEMD (NST*STGD)          // 98304
#define STGK (2*ASZ)              // kv 1-pass: A,B
#define EPIB (128*133*4)          // 68096 (splitT scratch)
#define SMEMK ((NST*STGK) > EPIB ? (NST*STGK) : EPIB)   // 68096
#define STGO (3*ASZ)              // out 2-pass: Ah,Al,B
#define SMEMO (NST*STGO)          // 98304

#define SWZ64(x) ((x) ^ (((x) >> 3) & 0x30))

// ------------------------------ scratch -----------------------------------
__device__ __align__(16) __half g_X  [(size_t)BNROWS*Dv];
__device__ __align__(16) __half g_WT [4][1024*1024];
__device__ __align__(16) __half g_QH [(size_t)BNROWS*Dv];
__device__ __align__(16) __half g_QLo[(size_t)BNROWS*Dv];
__device__ __align__(16) __half g_KT [(size_t)Bv*Dv*Nv];   // hi only
__device__ __align__(16) __half g_VT [(size_t)Bv*Dv*Nv];   // hi only
__device__ __align__(16) __half g_KVT[(size_t)Bv*Dv*Dv];   // hi only

// ------------------------------ helpers ------------------------------------
__device__ __forceinline__ uint32_t s2u(const void* p) {
    uint32_t a;
    asm("{ .reg .u64 t; cvta.to.shared.u64 t, %1; cvt.u32.u64 %0, t; }" : "=r"(a) : "l"(p));
    return a;
}
__device__ __forceinline__ void cpa16(uint32_t dst, const void* src) {
    asm volatile("cp.async.cg.shared.global [%0], [%1], 16;" :: "r"(dst), "l"(src));
}
#define CPC() asm volatile("cp.async.commit_group;" ::: "memory")

__device__ __forceinline__ void ldsm4(uint32_t* r, uint32_t addr) {
    asm volatile("ldmatrix.sync.aligned.m8n8.x4.shared.b16 {%0,%1,%2,%3}, [%4];"
                 : "=r"(r[0]), "=r"(r[1]), "=r"(r[2]), "=r"(r[3]) : "r"(addr));
}
__device__ __forceinline__ void mmaf16(float* c, const uint32_t* a, const uint32_t* b) {
    asm volatile(
        "mma.sync.aligned.m16n8k16.row.col.f32.f16.f16.f32 "
        "{%0,%1,%2,%3}, {%4,%5,%6,%7}, {%8,%9}, {%0,%1,%2,%3};"
        : "+f"(c[0]), "+f"(c[1]), "+f"(c[2]), "+f"(c[3])
        : "r"(a[0]), "r"(a[1]), "r"(a[2]), "r"(a[3]), "r"(b[0]), "r"(b[1]));
}

__device__ __forceinline__ uint32_t pack_hl(float f) {
    __half h = __float2half_rn(f);
    __half l = __float2half_rn(f - __half2float(h));
    return ((uint32_t)__half_as_ushort(h) << 16) | __half_as_ushort(l);
}
__device__ __forceinline__ void split2pack(float f0, float f1, uint32_t& wh, uint32_t& wl) {
    __half h0 = __float2half_rn(f0);
    __half h1 = __float2half_rn(f1);
    __half l0 = __float2half_rn(f0 - __half2float(h0));
    __half l1 = __float2half_rn(f1 - __half2float(h1));
    wh = ((uint32_t)__half_as_ushort(h1) << 16) | __half_as_ushort(h0);
    wl = ((uint32_t)__half_as_ushort(l1) << 16) | __half_as_ushort(l0);
}

// ldmatrix offsets for 32x32 warp tile (wm/wn warp origin within 128x128 CTA tile)
struct Offs { uint32_t a[2][2]; uint32_t b[2][2]; };
__device__ __forceinline__ Offs mkoffs(int wm, int wn, int lane) {
    Offs o;
    uint32_t arow = (uint32_t)(wm + (lane & 15));
    uint32_t acol = (uint32_t)((lane >> 4) * 16);
    uint32_t brow = (uint32_t)(wn + ((lane >> 4) << 3) + (lane & 7));
    uint32_t bcol = (uint32_t)(((lane >> 3) & 1) * 16);
#pragma unroll
    for (int ks = 0; ks < 2; ks++) {
#pragma unroll
        for (int mi = 0; mi < 2; mi++)
            o.a[ks][mi] = SWZ64((arow + mi * 16) * 64 + ks * 32 + acol);
#pragma unroll
        for (int g = 0; g < 2; g++)
            o.b[ks][g] = SWZ64((brow + g * 16) * 64 + ks * 32 + bcol);
    }
    return o;
}

// Split-transpose epilogue: 128x128 C tile -> hi halves, rows bn+d, cols bm..
__device__ __forceinline__ void epi_T(
    const float (&acc)[2][4][4], char* sm,
    int wm, int wn, int lane, int tid,
    __half* __restrict__ OH, size_t base, int ldo)
{
    __syncthreads();
    uint32_t* s32 = (uint32_t*)sm;
#pragma unroll
    for (int mi = 0; mi < 2; mi++) {
        int r = wm + mi * 16 + (lane >> 2);
#pragma unroll
        for (int ni = 0; ni < 4; ni++) {
            int c = wn + ni * 8 + (lane & 3) * 2;
            s32[r * 133 + c]           = pack_hl(acc[mi][ni][0]);
            s32[r * 133 + c + 1]       = pack_hl(acc[mi][ni][1]);
            s32[(r + 8) * 133 + c]     = pack_hl(acc[mi][ni][2]);
            s32[(r + 8) * 133 + c + 1] = pack_hl(acc[mi][ni][3]);
        }
    }
    __syncthreads();
    int d = tid >> 2, nb = (tid & 3) * 32;
    __half* rh = OH + base + (size_t)d * ldo + nb;
#pragma unroll
    for (int j = 0; j < 4; j++) {
        alignas(16) __half hb[8];
#pragma unroll
        for (int i = 0; i < 8; i++)
            hb[i] = __ushort_as_half((unsigned short)(s32[(nb + j * 8 + i) * 133 + d] >> 16));
        *(uint4*)(rh + j * 8) = *(const uint4*)hb;
    }
}

// --------------- dual-B 1-pass GEMM (projections) ---------------------------
// GATE=1: split(C1*C2) straight hi/lo. GATE=0: C1,C2 -> splitT hi-only.
template<int GATE>
__global__ __launch_bounds__(GT, 1)
void gemm1_dual(const __half* __restrict__ Ag,
                const __half* __restrict__ B1, const __half* __restrict__ B2,
                __half* __restrict__ O1H, __half* __restrict__ O1L,
                __half* __restrict__ O2H,
                int N, int Kg)
{
    extern __shared__ char sm[];
    const uint32_t smu = s2u(sm);
    const int tid = threadIdx.x, lane = tid & 31, wid = tid >> 5;
    const int bm = blockIdx.y * 128, bn = blockIdx.x * 128;
    const int wm = (wid & 3) * 32, wn = (wid >> 2) * 32;

    const int rr = tid >> 2, cg = tid & 3;
    const uint32_t so = SWZ64((uint32_t)(rr * 64 + cg * 16));
    const __half* gA = Ag + (size_t)(bm + rr) * Kg + cg * 8;
    const __half* g1 = B1 + (size_t)(bn + rr) * Kg + cg * 8;
    const __half* g2 = B2 + (size_t)(bn + rr) * Kg + cg * 8;

    const Offs of = mkoffs(wm, wn, lane);

    float a1[2][4][4], a2[2][4][4];
#pragma unroll
    for (int mi = 0; mi < 2; mi++)
#pragma unroll
        for (int ni = 0; ni < 4; ni++)
#pragma unroll
            for (int j = 0; j < 4; j++) { a1[mi][ni][j] = 0.0f; a2[mi][ni][j] = 0.0f; }

    const int nch = Kg / 32;
    auto load_stage = [&](int c) {
        const uint32_t st = smu + (uint32_t)(c & (NST - 1)) * STGD;
        const int k0 = c * 32;
        cpa16(st + so,          gA + k0);
        cpa16(st + ASZ + so,    g1 + k0);
        cpa16(st + 2*ASZ + so,  g2 + k0);
        CPC();
    };

    load_stage(0); load_stage(1); load_stage(2);

    for (int c = 0; c < nch; ++c) {
        asm volatile("cp.async.wait_group 2;" ::: "memory");
        __syncthreads();
        if (c + 3 < nch) load_stage(c + 3);

        const uint32_t st = smu + (uint32_t)(c & (NST - 1)) * STGD;
#pragma unroll
        for (int ks = 0; ks < 2; ks++) {
            uint32_t ah[2][4];
#pragma unroll
            for (int mi = 0; mi < 2; mi++)
                ldsm4(ah[mi], st + of.a[ks][mi]);
#pragma unroll
            for (int g = 0; g < 2; g++) {
                uint32_t t1[4], t2[4];
                ldsm4(t1, st + ASZ + of.b[ks][g]);
                ldsm4(t2, st + 2*ASZ + of.b[ks][g]);
#pragma unroll
                for (int mi = 0; mi < 2; mi++) {
                    mmaf16(a1[mi][2*g],   ah[mi], t1);
                    mmaf16(a1[mi][2*g+1], ah[mi], t1 + 2);
                    mmaf16(a2[mi][2*g],   ah[mi], t2);
                    mmaf16(a2[mi][2*g+1], ah[mi], t2 + 2);
                }
            }
        }
    }

    if (GATE == 1) {
#pragma unroll
        for (int mi = 0; mi < 2; mi++) {
            int r = bm + wm + mi * 16 + (lane >> 2);
#pragma unroll
            for (int ni = 0; ni < 4; ni++) {
                int c = bn + wn + ni * 8 + (lane & 3) * 2;
                uint32_t wh, wl;
                split2pack(a1[mi][ni][0]*a2[mi][ni][0], a1[mi][ni][1]*a2[mi][ni][1], wh, wl);
                *(uint32_t*)(O1H + (size_t)r * N + c) = wh;
                *(uint32_t*)(O1L + (size_t)r * N + c) = wl;
                split2pack(a1[mi][ni][2]*a2[mi][ni][2], a1[mi][ni][3]*a2[mi][ni][3], wh, wl);
                *(uint32_t*)(O1H + (size_t)(r + 8) * N + c) = wh;
                *(uint32_t*)(O1L + (size_t)(r + 8) * N + c) = wl;
            }
        }
    } else {
        size_t batch = (size_t)(bm >> 12);
        size_t base = batch * (size_t)Dv * Nv + (size_t)bn * Nv + (bm & 4095);
        epi_T(a1, sm, wm, wn, lane, tid, O1H, base, Nv);
        epi_T(a2, sm, wm, wn, lane, tid, O2H, base, Nv);
    }
}

// --------------- single-B 1-pass GEMM (kv) ----------------------------------
// C = A[M,K] @ (B[N,K])^T -> splitT hi-only into [N-rows? no: rows bn+d]
__global__ __launch_bounds__(GT, 1)
void gemm1_kv(const __half* __restrict__ Ag, const __half* __restrict__ Bg,
              __half* __restrict__ OH, int M, int N, int Kg,
              long sA, long sB, long sO)
{
    extern __shared__ char sm[];
    const uint32_t smu = s2u(sm);
    const int tid = threadIdx.x, lane = tid & 31, wid = tid >> 5;
    const int bm = blockIdx.y * 128, bn = blockIdx.x * 128;
    const int wm = (wid & 3) * 32, wn = (wid >> 2) * 32;

    const __half* Ap = Ag + (size_t)blockIdx.z * sA;
    const __half* Bp = Bg + (size_t)blockIdx.z * sB;

    const int rr = tid >> 2, cg = tid & 3;
    const uint32_t so = SWZ64((uint32_t)(rr * 64 + cg * 16));
    const __half* gA = Ap + (size_t)(bm + rr) * Kg + cg * 8;
    const __half* gB = Bp + (size_t)(bn + rr) * Kg + cg * 8;

    const Offs of = mkoffs(wm, wn, lane);

    float acc[2][4][4];
#pragma unroll
    for (int mi = 0; mi < 2; mi++)
#pragma unroll
        for (int ni = 0; ni < 4; ni++)
#pragma unroll
            for (int j = 0; j < 4; j++) acc[mi][ni][j] = 0.0f;

    const int nch = Kg / 32;
    auto load_stage = [&](int c) {
        const uint32_t st = smu + (uint32_t)(c & (NST - 1)) * STGK;
        const int k0 = c * 32;
        cpa16(st + so,        gA + k0);
        cpa16(st + ASZ + so,  gB + k0);
        CPC();
    };

    load_stage(0); load_stage(1); load_stage(2);

    for (int c = 0; c < nch; ++c) {
        asm volatile("cp.async.wait_group 2;" ::: "memory");
        __syncthreads();
        if (c + 3 < nch) load_stage(c + 3);

        const uint32_t st = smu + (uint32_t)(c & (NST - 1)) * STGK;
#pragma unroll
        for (int ks = 0; ks < 2; ks++) {
            uint32_t ah[2][4];
#pragma unroll
            for (int mi = 0; mi < 2; mi++)
                ldsm4(ah[mi], st + of.a[ks][mi]);
#pragma unroll
            for (int g = 0; g < 2; g++) {
                uint32_t tb[4];
                ldsm4(tb, st + ASZ + of.b[ks][g]);
#pragma unroll
                for (int mi = 0; mi < 2; mi++) {
                    mmaf16(acc[mi][2*g],   ah[mi], tb);
                    mmaf16(acc[mi][2*g+1], ah[mi], tb + 2);
                }
            }
        }
    }

    size_t base = (size_t)blockIdx.z * sO + (size_t)bn * M + bm;
    epi_T(acc, sm, wm, wn, lane, tid, OH, base, M);
}

// --------------- single-B 2-pass GEMM (out) ---------------------------------
// C = (Ah+Al)[M,K] @ (B[N,K])^T -> fp32 straight
__global__ __launch_bounds__(GT, 1)
void gemm2_out(const __half* __restrict__ Ahg, const __half* __restrict__ Alg,
               const __half* __restrict__ Bg, float* __restrict__ Cf,
               int M, int N, int Kg, long sA, long sB, long sO)
{
    extern __shared__ char sm[];
    const uint32_t smu = s2u(sm);
    const int tid = threadIdx.x, lane = tid & 31, wid = tid >> 5;
    const int bm = blockIdx.y * 128, bn = blockIdx.x * 128;
    const int wm = (wid & 3) * 32, wn = (wid >> 2) * 32;

    const __half* Ah = Ahg + (size_t)blockIdx.z * sA;
    const __half* Al = Alg + (size_t)blockIdx.z * sA;
    const __half* Bp = Bg  + (size_t)blockIdx.z * sB;

    const int rr = tid >> 2, cg = tid & 3;
    const uint32_t so = SWZ64((uint32_t)(rr * 64 + cg * 16));
    const __half* gAh = Ah + (size_t)(bm + rr) * Kg + cg * 8;
    const __half* gAl = Al + (size_t)(bm + rr) * Kg + cg * 8;
    const __half* gB  = Bp + (size_t)(bn + rr) * Kg + cg * 8;

    const Offs of = mkoffs(wm, wn, lane);

    float acc[2][4][4];
#pragma unroll
    for (int mi = 0; mi < 2; mi++)
#pragma unroll
        for (int ni = 0; ni < 4; ni++)
#pragma unroll
            for (int j = 0; j < 4; j++) acc[mi][ni][j] = 0.0f;

    const int nch = Kg / 32;
    auto load_stage = [&](int c) {
        const uint32_t st = smu + (uint32_t)(c & (NST - 1)) * STGO;
        const int k0 = c * 32;
        cpa16(st + so,          gAh + k0);
        cpa16(st + ASZ + so,    gAl + k0);
        cpa16(st + 2*ASZ + so,  gB + k0);
        CPC();
    };

    load_stage(0); load_stage(1); load_stage(2);

    for (int c = 0; c < nch; ++c) {
        asm volatile("cp.async.wait_group 2;" ::: "memory");
        __syncthreads();
        if (c + 3 < nch) load_stage(c + 3);

        const uint32_t st = smu + (uint32_t)(c & (NST - 1)) * STGO;
#pragma unroll
        for (int ks = 0; ks < 2; ks++) {
            uint32_t ah[2][4], al[2][4];
#pragma unroll
            for (int mi = 0; mi < 2; mi++) {
                ldsm4(ah[mi], st + of.a[ks][mi]);
                ldsm4(al[mi], st + ASZ + of.a[ks][mi]);
            }
#pragma unroll
            for (int g = 0; g < 2; g++) {
                uint32_t tb[4];
                ldsm4(tb, st + 2*ASZ + of.b[ks][g]);
#pragma unroll
                for (int mi = 0; mi < 2; mi++) {
                    mmaf16(acc[mi][2*g],   ah[mi], tb);
                    mmaf16(acc[mi][2*g],   al[mi], tb);
                    mmaf16(acc[mi][2*g+1], ah[mi], tb + 2);
                    mmaf16(acc[mi][2*g+1], al[mi], tb + 2);
                }
            }
        }
    }

    float* Cb = Cf + (size_t)blockIdx.z * sO;
#pragma unroll
    for (int mi = 0; mi < 2; mi++) {
        int rA = bm + wm + mi * 16 + (lane >> 2);
#pragma unroll
        for (int ni = 0; ni < 4; ni++) {
            int col = bn + wn + ni * 8 + (lane & 3) * 2;
            *(float2*)(Cb + (size_t)rA * N + col)       = make_float2(acc[mi][ni][0], acc[mi][ni][1]);
            *(float2*)(Cb + (size_t)(rA + 8) * N + col) = make_float2(acc[mi][ni][2], acc[mi][ni][3]);
        }
    }
}

// --------------------------- conversion kernels ----------------------------
__global__ void conv_x(const float* __restrict__ in, __half* __restrict__ o) {
    size_t i = (size_t)blockIdx.x * blockDim.x + threadIdx.x;
    float4 f = ((const float4*)in)[i];
    ((__half2*)o)[i*2]   = __halves2half2(__float2half_rn(f.x), __float2half_rn(f.y));
    ((__half2*)o)[i*2+1] = __halves2half2(__float2half_rn(f.z), __float2half_rn(f.w));
}

__global__ void conv_wT(const float* w0, const float* w1, const float* w2, const float* w3,
                        __half* __restrict__ O) {
    const float* in = (blockIdx.z == 0) ? w0 : (blockIdx.z == 1) ? w1
                     : (blockIdx.z == 2) ? w2 : w3;
    __half* o = O + (size_t)blockIdx.z * Dv * Dv;
    __shared__ float t[32][33];
    int c0 = blockIdx.x * 32, r0 = blockIdx.y * 32;
    int tx = threadIdx.x, ty = threadIdx.y;
#pragma unroll
    for (int i = 0; i < 4; i++)
        t[ty + i*8][tx] = in[(size_t)(r0 + ty + i*8) * Dv + c0 + tx];
    __syncthreads();
#pragma unroll
    for (int i = 0; i < 4; i++) {
        int oc = c0 + ty + i*8, od = r0 + tx;
        o[(size_t)oc * Dv + od] = __float2half_rn(t[tx][ty + i*8]);
    }
}

// ------------------------------- launch ------------------------------------
extern "C" void kernel_launch(void* const* d_in, const int* in_sizes, int n_in,
                              void* d_out, int out_size) {
    const float* x   = (const float*)d_in[0];
    const float* w[4] = { (const float*)d_in[1], (const float*)d_in[2],
                          (const float*)d_in[3], (const float*)d_in[4] };
    float* out = (float*)d_out;

    __half *X,*WT,*QH,*QLo,*KT,*VT,*KVT;
    cudaGetSymbolAddress((void**)&X,   g_X);
    cudaGetSymbolAddress((void**)&WT,  g_WT);
    cudaGetSymbolAddress((void**)&QH,  g_QH);  cudaGetSymbolAddress((void**)&QLo, g_QLo);
    cudaGetSymbolAddress((void**)&KT,  g_KT);  cudaGetSymbolAddress((void**)&VT,  g_VT);
    cudaGetSymbolAddress((void**)&KVT, g_KVT);

    cudaFuncSetAttribute(gemm1_dual<0>, cudaFuncAttributeMaxDynamicSharedMemorySize, SMEMD);
    cudaFuncSetAttribute(gemm1_dual<1>, cudaFuncAttributeMaxDynamicSharedMemorySize, SMEMD);
    cudaFuncSetAttribute(gemm1_kv,      cudaFuncAttributeMaxDynamicSharedMemorySize, SMEMK);
    cudaFuncSetAttribute(gemm2_out,     cudaFuncAttributeMaxDynamicSharedMemorySize, SMEMO);

    const size_t DDe = (size_t)Dv * Dv;
    const size_t PNe = (size_t)BNROWS * Dv;
    dim3 tb32(32, 8);

    // 1) conversions
    conv_x<<<(unsigned)(PNe/4/256), 256>>>(x, X);
    conv_wT<<<dim3(Dv/32, Dv/32, 4), tb32>>>(w[0], w[1], w[2], w[3], WT);

    // 2) q = (x@Wql)*(x@Wqr) -> split straight hi/lo
    gemm1_dual<1><<<dim3(Dv/128, BNROWS/128), GT, SMEMD>>>(
        X, WT + 0*DDe, WT + 1*DDe, QH, QLo, nullptr, Dv, Dv);

    // 3) k, v -> k^T, v^T hi-only [Dv][Nv] per batch
    gemm1_dual<0><<<dim3(Dv/128, BNROWS/128), GT, SMEMD>>>(
        X, WT + 2*DDe, WT + 3*DDe, KT, nullptr, VT, Dv, Dv);

    // 4) kv[b] = k^T@v (1-pass) -> kv^T hi-only [Dv][Dv]
    gemm1_kv<<<dim3(Dv/128, Dv/128, Bv), GT, SMEMK>>>(
        KT, VT, KVT, Dv, Dv, Nv, (long)Dv*Nv, (long)Dv*Nv, (long)DDe);

    // 5) out[b] = q@kv (2-pass, A=q hi/lo) -> fp32
    gemm2_out<<<dim3(Dv/128, Nv/128, Bv), GT, SMEMO>>>(
        QH, QLo, KVT, out, Nv, Dv, Dv, (long)Nv*Dv, (long)DDe, (long)Nv*Dv);
}

// round 11
// speedup vs baseline: 5.2660x; 1.1467x over previous
#include <cuda_runtime.h>
#include <cuda_fp16.h>
#include <cstdint>

// LinearAttention B=4, N=4096, D=1024 fp32
// R11: ALL GEMMs 1-pass fp16 (6x 34.4GF units). q stored hi-only.
//      512-thread CTAs, 128x128 tiles, fused gate / split-transpose epilogues.

#define Bv 4
#define Nv 4096
#define Dv 1024
#define BNROWS (Bv*Nv)            // 16384

#define GT 512                    // 16 warps
#define ASZ 8192                  // 128 rows x 64B operand tile
#define NST 4

#define STGD (3*ASZ)              // dual 1-pass: A,B1,B2
#define SMEMD (NST*STGD)          // 98304
#define STGS (2*ASZ)              // single 1-pass: A,B
#define EPIB (128*133*4)          // 68096 (splitT scratch)
#define SMEMS ((NST*STGS) > EPIB ? (NST*STGS) : EPIB)   // 68096

#define SWZ64(x) ((x) ^ (((x) >> 3) & 0x30))

// ------------------------------ scratch -----------------------------------
__device__ __align__(16) __half g_X  [(size_t)BNROWS*Dv];
__device__ __align__(16) __half g_WT [4][1024*1024];
__device__ __align__(16) __half g_Q  [(size_t)BNROWS*Dv];  // hi only
__device__ __align__(16) __half g_KT [(size_t)Bv*Dv*Nv];   // hi only
__device__ __align__(16) __half g_VT [(size_t)Bv*Dv*Nv];   // hi only
__device__ __align__(16) __half g_KVT[(size_t)Bv*Dv*Dv];   // hi only

// ------------------------------ helpers ------------------------------------
__device__ __forceinline__ uint32_t s2u(const void* p) {
    uint32_t a;
    asm("{ .reg .u64 t; cvta.to.shared.u64 t, %1; cvt.u32.u64 %0, t; }" : "=r"(a) : "l"(p));
    return a;
}
__device__ __forceinline__ void cpa16(uint32_t dst, const void* src) {
    asm volatile("cp.async.cg.shared.global [%0], [%1], 16;" :: "r"(dst), "l"(src));
}
#define CPC() asm volatile("cp.async.commit_group;" ::: "memory")

__device__ __forceinline__ void ldsm4(uint32_t* r, uint32_t addr) {
    asm volatile("ldmatrix.sync.aligned.m8n8.x4.shared.b16 {%0,%1,%2,%3}, [%4];"
                 : "=r"(r[0]), "=r"(r[1]), "=r"(r[2]), "=r"(r[3]) : "r"(addr));
}
__device__ __forceinline__ void mmaf16(float* c, const uint32_t* a, const uint32_t* b) {
    asm volatile(
        "mma.sync.aligned.m16n8k16.row.col.f32.f16.f16.f32 "
        "{%0,%1,%2,%3}, {%4,%5,%6,%7}, {%8,%9}, {%0,%1,%2,%3};"
        : "+f"(c[0]), "+f"(c[1]), "+f"(c[2]), "+f"(c[3])
        : "r"(a[0]), "r"(a[1]), "r"(a[2]), "r"(a[3]), "r"(b[0]), "r"(b[1]));
}

__device__ __forceinline__ uint32_t packh2(float f0, float f1) {
    return ((uint32_t)__half_as_ushort(__float2half_rn(f1)) << 16)
         | __half_as_ushort(__float2half_rn(f0));
}

// ldmatrix offsets for 32x32 warp tile
struct Offs { uint32_t a[2][2]; uint32_t b[2][2]; };
__device__ __forceinline__ Offs mkoffs(int wm, int wn, int lane) {
    Offs o;
    uint32_t arow = (uint32_t)(wm + (lane & 15));
    uint32_t acol = (uint32_t)((lane >> 4) * 16);
    uint32_t brow = (uint32_t)(wn + ((lane >> 4) << 3) + (lane & 7));
    uint32_t bcol = (uint32_t)(((lane >> 3) & 1) * 16);
#pragma unroll
    for (int ks = 0; ks < 2; ks++) {
#pragma unroll
        for (int mi = 0; mi < 2; mi++)
            o.a[ks][mi] = SWZ64((arow + mi * 16) * 64 + ks * 32 + acol);
#pragma unroll
        for (int g = 0; g < 2; g++)
            o.b[ks][g] = SWZ64((brow + g * 16) * 64 + ks * 32 + bcol);
    }
    return o;
}

// Transpose epilogue: 128x128 C tile -> fp16 rows (bn+d), cols bm.. (hi only)
// SMEM scratch holds packed fp16 pairs per row: uses s16 layout 128x133 u32.
__device__ __forceinline__ void epi_T(
    const float (&acc)[2][4][4], char* sm,
    int wm, int wn, int lane, int tid,
    __half* __restrict__ OH, size_t base, int ldo)
{
    __syncthreads();
    // store as fp16 (one half per u32 slot's low 16 bits would waste; pack 2 cols/slot)
    // simple: one fp32->fp16 value per 2-byte slot in a 128x(132) half array
    __half* s16 = (__half*)sm;
    const int LDS = 136;                      // halfs per row (8-byte padded)
#pragma unroll
    for (int mi = 0; mi < 2; mi++) {
        int r = wm + mi * 16 + (lane >> 2);
#pragma unroll
        for (int ni = 0; ni < 4; ni++) {
            int c = wn + ni * 8 + (lane & 3) * 2;
            s16[r * LDS + c]           = __float2half_rn(acc[mi][ni][0]);
            s16[r * LDS + c + 1]       = __float2half_rn(acc[mi][ni][1]);
            s16[(r + 8) * LDS + c]     = __float2half_rn(acc[mi][ni][2]);
            s16[(r + 8) * LDS + c + 1] = __float2half_rn(acc[mi][ni][3]);
        }
    }
    __syncthreads();
    int d = tid >> 2, nb = (tid & 3) * 32;
    __half* rh = OH + base + (size_t)d * ldo + nb;
#pragma unroll
    for (int j = 0; j < 4; j++) {
        alignas(16) __half hb[8];
#pragma unroll
        for (int i = 0; i < 8; i++)
            hb[i] = s16[(nb + j * 8 + i) * LDS + d];
        *(uint4*)(rh + j * 8) = *(const uint4*)hb;
    }
}

// --------------- dual-B 1-pass GEMM (projections) ---------------------------
// GATE=1: q = C1*C2 -> straight fp16 hi. GATE=0: C1,C2 -> transposed fp16 hi.
template<int GATE>
__global__ __launch_bounds__(GT, 1)
void gemm1_dual(const __half* __restrict__ Ag,
                const __half* __restrict__ B1, const __half* __restrict__ B2,
                __half* __restrict__ O1, __half* __restrict__ O2,
                int N, int Kg)
{
    extern __shared__ char sm[];
    const uint32_t smu = s2u(sm);
    const int tid = threadIdx.x, lane = tid & 31, wid = tid >> 5;
    const int bm = blockIdx.y * 128, bn = blockIdx.x * 128;
    const int wm = (wid & 3) * 32, wn = (wid >> 2) * 32;

    const int rr = tid >> 2, cg = tid & 3;
    const uint32_t so = SWZ64((uint32_t)(rr * 64 + cg * 16));
    const __half* gA = Ag + (size_t)(bm + rr) * Kg + cg * 8;
    const __half* g1 = B1 + (size_t)(bn + rr) * Kg + cg * 8;
    const __half* g2 = B2 + (size_t)(bn + rr) * Kg + cg * 8;

    const Offs of = mkoffs(wm, wn, lane);

    float a1[2][4][4], a2[2][4][4];
#pragma unroll
    for (int mi = 0; mi < 2; mi++)
#pragma unroll
        for (int ni = 0; ni < 4; ni++)
#pragma unroll
            for (int j = 0; j < 4; j++) { a1[mi][ni][j] = 0.0f; a2[mi][ni][j] = 0.0f; }

    const int nch = Kg / 32;
    auto load_stage = [&](int c) {
        const uint32_t st = smu + (uint32_t)(c & (NST - 1)) * STGD;
        const int k0 = c * 32;
        cpa16(st + so,          gA + k0);
        cpa16(st + ASZ + so,    g1 + k0);
        cpa16(st + 2*ASZ + so,  g2 + k0);
        CPC();
    };

    load_stage(0); load_stage(1); load_stage(2);

    for (int c = 0; c < nch; ++c) {
        asm volatile("cp.async.wait_group 2;" ::: "memory");
        __syncthreads();
        if (c + 3 < nch) load_stage(c + 3);

        const uint32_t st = smu + (uint32_t)(c & (NST - 1)) * STGD;
#pragma unroll
        for (int ks = 0; ks < 2; ks++) {
            uint32_t ah[2][4];
#pragma unroll
            for (int mi = 0; mi < 2; mi++)
                ldsm4(ah[mi], st + of.a[ks][mi]);
#pragma unroll
            for (int g = 0; g < 2; g++) {
                uint32_t t1[4], t2[4];
                ldsm4(t1, st + ASZ + of.b[ks][g]);
                ldsm4(t2, st + 2*ASZ + of.b[ks][g]);
#pragma unroll
                for (int mi = 0; mi < 2; mi++) {
                    mmaf16(a1[mi][2*g],   ah[mi], t1);
                    mmaf16(a1[mi][2*g+1], ah[mi], t1 + 2);
                    mmaf16(a2[mi][2*g],   ah[mi], t2);
                    mmaf16(a2[mi][2*g+1], ah[mi], t2 + 2);
                }
            }
        }
    }

    if (GATE == 1) {
#pragma unroll
        for (int mi = 0; mi < 2; mi++) {
            int r = bm + wm + mi * 16 + (lane >> 2);
#pragma unroll
            for (int ni = 0; ni < 4; ni++) {
                int c = bn + wn + ni * 8 + (lane & 3) * 2;
                *(uint32_t*)(O1 + (size_t)r * N + c) =
                    packh2(a1[mi][ni][0]*a2[mi][ni][0], a1[mi][ni][1]*a2[mi][ni][1]);
                *(uint32_t*)(O1 + (size_t)(r + 8) * N + c) =
                    packh2(a1[mi][ni][2]*a2[mi][ni][2], a1[mi][ni][3]*a2[mi][ni][3]);
            }
        }
    } else {
        size_t batch = (size_t)(bm >> 12);
        size_t base = batch * (size_t)Dv * Nv + (size_t)bn * Nv + (bm & 4095);
        epi_T(a1, sm, wm, wn, lane, tid, O1, base, Nv);
        epi_T(a2, sm, wm, wn, lane, tid, O2, base, Nv);
    }
}

// --------------- single-B 1-pass GEMM ---------------------------------------
// MODE 0: fp32 straight (out). MODE 1: transposed fp16 hi (kv).
template<int MODE>
__global__ __launch_bounds__(GT, 1)
void gemm1(const __half* __restrict__ Ag, const __half* __restrict__ Bg,
           float* __restrict__ Cf, __half* __restrict__ OH,
           int M, int N, int Kg, long sA, long sB, long sO)
{
    extern __shared__ char sm[];
    const uint32_t smu = s2u(sm);
    const int tid = threadIdx.x, lane = tid & 31, wid = tid >> 5;
    const int bm = blockIdx.y * 128, bn = blockIdx.x * 128;
    const int wm = (wid & 3) * 32, wn = (wid >> 2) * 32;

    const __half* Ap = Ag + (size_t)blockIdx.z * sA;
    const __half* Bp = Bg + (size_t)blockIdx.z * sB;

    const int rr = tid >> 2, cg = tid & 3;
    const uint32_t so = SWZ64((uint32_t)(rr * 64 + cg * 16));
    const __half* gA = Ap + (size_t)(bm + rr) * Kg + cg * 8;
    const __half* gB = Bp + (size_t)(bn + rr) * Kg + cg * 8;

    const Offs of = mkoffs(wm, wn, lane);

    float acc[2][4][4];
#pragma unroll
    for (int mi = 0; mi < 2; mi++)
#pragma unroll
        for (int ni = 0; ni < 4; ni++)
#pragma unroll
            for (int j = 0; j < 4; j++) acc[mi][ni][j] = 0.0f;

    const int nch = Kg / 32;
    auto load_stage = [&](int c) {
        const uint32_t st = smu + (uint32_t)(c & (NST - 1)) * STGS;
        const int k0 = c * 32;
        cpa16(st + so,        gA + k0);
        cpa16(st + ASZ + so,  gB + k0);
        CPC();
    };

    load_stage(0); load_stage(1); load_stage(2);

    for (int c = 0; c < nch; ++c) {
        asm volatile("cp.async.wait_group 2;" ::: "memory");
        __syncthreads();
        if (c + 3 < nch) load_stage(c + 3);

        const uint32_t st = smu + (uint32_t)(c & (NST - 1)) * STGS;
#pragma unroll
        for (int ks = 0; ks < 2; ks++) {
            uint32_t ah[2][4];
#pragma unroll
            for (int mi = 0; mi < 2; mi++)
                ldsm4(ah[mi], st + of.a[ks][mi]);
#pragma unroll
            for (int g = 0; g < 2; g++) {
                uint32_t tb[4];
                ldsm4(tb, st + ASZ + of.b[ks][g]);
#pragma unroll
                for (int mi = 0; mi < 2; mi++) {
                    mmaf16(acc[mi][2*g],   ah[mi], tb);
                    mmaf16(acc[mi][2*g+1], ah[mi], tb + 2);
                }
            }
        }
    }

    if (MODE == 0) {
        float* Cb = Cf + (size_t)blockIdx.z * sO;
#pragma unroll
        for (int mi = 0; mi < 2; mi++) {
            int rA = bm + wm + mi * 16 + (lane >> 2);
#pragma unroll
            for (int ni = 0; ni < 4; ni++) {
                int col = bn + wn + ni * 8 + (lane & 3) * 2;
                *(float2*)(Cb + (size_t)rA * N + col)       = make_float2(acc[mi][ni][0], acc[mi][ni][1]);
                *(float2*)(Cb + (size_t)(rA + 8) * N + col) = make_float2(acc[mi][ni][2], acc[mi][ni][3]);
            }
        }
    } else {
        size_t base = (size_t)blockIdx.z * sO + (size_t)bn * M + bm;
        epi_T(acc, sm, wm, wn, lane, tid, OH, base, M);
    }
}

// --------------------------- conversion kernels ----------------------------
__global__ void conv_x(const float* __restrict__ in, __half* __restrict__ o) {
    size_t i = (size_t)blockIdx.x * blockDim.x + threadIdx.x;
    float4 f = ((const float4*)in)[i];
    ((__half2*)o)[i*2]   = __halves2half2(__float2half_rn(f.x), __float2half_rn(f.y));
    ((__half2*)o)[i*2+1] = __halves2half2(__float2half_rn(f.z), __float2half_rn(f.w));
}

__global__ void conv_wT(const float* w0, const float* w1, const float* w2, const float* w3,
                        __half* __restrict__ O) {
    const float* in = (blockIdx.z == 0) ? w0 : (blockIdx.z == 1) ? w1
                     : (blockIdx.z == 2) ? w2 : w3;
    __half* o = O + (size_t)blockIdx.z * Dv * Dv;
    __shared__ float t[32][33];
    int c0 = blockIdx.x * 32, r0 = blockIdx.y * 32;
    int tx = threadIdx.x, ty = threadIdx.y;
#pragma unroll
    for (int i = 0; i < 4; i++)
        t[ty + i*8][tx] = in[(size_t)(r0 + ty + i*8) * Dv + c0 + tx];
    __syncthreads();
#pragma unroll
    for (int i = 0; i < 4; i++) {
        int oc = c0 + ty + i*8, od = r0 + tx;
        o[(size_t)oc * Dv + od] = __float2half_rn(t[tx][ty + i*8]);
    }
}

// ------------------------------- launch ------------------------------------
extern "C" void kernel_launch(void* const* d_in, const int* in_sizes, int n_in,
                              void* d_out, int out_size) {
    const float* x   = (const float*)d_in[0];
    const float* w[4] = { (const float*)d_in[1], (const float*)d_in[2],
                          (const float*)d_in[3], (const float*)d_in[4] };
    float* out = (float*)d_out;

    __half *X,*WT,*Q,*KT,*VT,*KVT;
    cudaGetSymbolAddress((void**)&X,   g_X);
    cudaGetSymbolAddress((void**)&WT,  g_WT);
    cudaGetSymbolAddress((void**)&Q,   g_Q);
    cudaGetSymbolAddress((void**)&KT,  g_KT);  cudaGetSymbolAddress((void**)&VT,  g_VT);
    cudaGetSymbolAddress((void**)&KVT, g_KVT);

    cudaFuncSetAttribute(gemm1_dual<0>, cudaFuncAttributeMaxDynamicSharedMemorySize, SMEMD);
    cudaFuncSetAttribute(gemm1_dual<1>, cudaFuncAttributeMaxDynamicSharedMemorySize, SMEMD);
    cudaFuncSetAttribute(gemm1<0>,      cudaFuncAttributeMaxDynamicSharedMemorySize, SMEMS);
    cudaFuncSetAttribute(gemm1<1>,      cudaFuncAttributeMaxDynamicSharedMemorySize, SMEMS);

    const size_t DDe = (size_t)Dv * Dv;
    const size_t PNe = (size_t)BNROWS * Dv;
    dim3 tb32(32, 8);

    // 1) conversions
    conv_x<<<(unsigned)(PNe/4/256), 256>>>(x, X);
    conv_wT<<<dim3(Dv/32, Dv/32, 4), tb32>>>(w[0], w[1], w[2], w[3], WT);

    // 2) q = (x@Wql)*(x@Wqr) -> straight fp16 hi
    gemm1_dual<1><<<dim3(Dv/128, BNROWS/128), GT, SMEMD>>>(
        X, WT + 0*DDe, WT + 1*DDe, Q, nullptr, Dv, Dv);

    // 3) k, v -> k^T, v^T fp16 hi [Dv][Nv] per batch
    gemm1_dual<0><<<dim3(Dv/128, BNROWS/128), GT, SMEMD>>>(
        X, WT + 2*DDe, WT + 3*DDe, KT, VT, Dv, Dv);

    // 4) kv[b] = k^T@v -> kv^T fp16 hi [Dv][Dv]
    gemm1<1><<<dim3(Dv/128, Dv/128, Bv), GT, SMEMS>>>(
        KT, VT, nullptr, KVT, Dv, Dv, Nv, (long)Dv*Nv, (long)Dv*Nv, (long)DDe);

    // 5) out[b] = q@kv -> fp32
    gemm1<0><<<dim3(Dv/128, Nv/128, Bv), GT, SMEMS>>>(
        Q, KVT, out, nullptr, Nv, Dv, Dv, (long)Nv*Dv, (long)DDe, (long)Nv*Dv);
}

// round 12
// speedup vs baseline: 5.3304x; 1.0122x over previous
#include <cuda_runtime.h>
#include <cuda_fp16.h>
#include <cstdint>

// LinearAttention B=4, N=4096, D=1024 fp32
// R12: all 1-pass fp16; ratio-4 warp tiles (less smem traffic per MMA).
//   dual (proj): 8 warps, 64x32 warp tile, CTA 128x128
//   single (kv/out): 8 warps, 64x64 warp tile, CTA 128x256

#define Bv 4
#define Nv 4096
#define Dv 1024
#define BNROWS (Bv*Nv)            // 16384

#define GT 256                    // 8 warps
#define NST 4
#define ASZ  8192                 // 128 rows x 64B
#define BSZ 16384                 // 256 rows x 64B

#define STGD (3*ASZ)              // dual: A,B1,B2        (24KB)
#define SMEMD (NST*STGD)          // 98304
#define STGS (ASZ+BSZ)            // single: A(128),B(256) (24KB)
#define SMEMS (NST*STGS)          // 98304 (>= 128*264*2 epi scratch)

#define SWZ64(x) ((x) ^ (((x) >> 3) & 0x30))

// ------------------------------ scratch -----------------------------------
__device__ __align__(16) __half g_X  [(size_t)BNROWS*Dv];
__device__ __align__(16) __half g_WT [4][1024*1024];
__device__ __align__(16) __half g_Q  [(size_t)BNROWS*Dv];
__device__ __align__(16) __half g_KT [(size_t)Bv*Dv*Nv];
__device__ __align__(16) __half g_VT [(size_t)Bv*Dv*Nv];
__device__ __align__(16) __half g_KVT[(size_t)Bv*Dv*Dv];

// ------------------------------ helpers ------------------------------------
__device__ __forceinline__ uint32_t s2u(const void* p) {
    uint32_t a;
    asm("{ .reg .u64 t; cvta.to.shared.u64 t, %1; cvt.u32.u64 %0, t; }" : "=r"(a) : "l"(p));
    return a;
}
__device__ __forceinline__ void cpa16(uint32_t dst, const void* src) {
    asm volatile("cp.async.cg.shared.global [%0], [%1], 16;" :: "r"(dst), "l"(src));
}
#define CPC() asm volatile("cp.async.commit_group;" ::: "memory")

__device__ __forceinline__ void ldsm4(uint32_t* r, uint32_t addr) {
    asm volatile("ldmatrix.sync.aligned.m8n8.x4.shared.b16 {%0,%1,%2,%3}, [%4];"
                 : "=r"(r[0]), "=r"(r[1]), "=r"(r[2]), "=r"(r[3]) : "r"(addr));
}
__device__ __forceinline__ void mmaf16(float* c, const uint32_t* a, const uint32_t* b) {
    asm volatile(
        "mma.sync.aligned.m16n8k16.row.col.f32.f16.f16.f32 "
        "{%0,%1,%2,%3}, {%4,%5,%6,%7}, {%8,%9}, {%0,%1,%2,%3};"
        : "+f"(c[0]), "+f"(c[1]), "+f"(c[2]), "+f"(c[3])
        : "r"(a[0]), "r"(a[1]), "r"(a[2]), "r"(a[3]), "r"(b[0]), "r"(b[1]));
}
__device__ __forceinline__ uint32_t packh2(float f0, float f1) {
    return ((uint32_t)__half_as_ushort(__float2half_rn(f1)) << 16)
         | __half_as_ushort(__float2half_rn(f0));
}

// --------------- dual-B 1-pass GEMM (projections) ---------------------------
// CTA 128x128, 8 warps, warp 64x32. GATE=1: q=C1*C2 straight fp16.
// GATE=0: C1,C2 -> transposed fp16 into per-batch [Dv][Nv].
template<int GATE>
__global__ __launch_bounds__(GT, 1)
void gemm1_dual(const __half* __restrict__ Ag,
                const __half* __restrict__ B1, const __half* __restrict__ B2,
                __half* __restrict__ O1, __half* __restrict__ O2,
                int N, int Kg)
{
    extern __shared__ char sm[];
    const uint32_t smu = s2u(sm);
    const int tid = threadIdx.x, lane = tid & 31, wid = tid >> 5;
    const int bm = blockIdx.y * 128, bn = blockIdx.x * 128;
    const int wm = (wid & 1) * 64, wn = (wid >> 1) * 32;

    const int rr = tid >> 2, cg = tid & 3;
    const uint32_t so0 = SWZ64((uint32_t)(rr * 64 + cg * 16));
    const uint32_t so1 = SWZ64((uint32_t)((rr + 64) * 64 + cg * 16));
    const __half* gA = Ag + (size_t)(bm + rr) * Kg + cg * 8;
    const __half* g1 = B1 + (size_t)(bn + rr) * Kg + cg * 8;
    const __half* g2 = B2 + (size_t)(bn + rr) * Kg + cg * 8;
    const size_t rstep = (size_t)64 * Kg;

    uint32_t aoff[2][4], boff[2][2];
    {
        uint32_t arow = (uint32_t)(wm + (lane & 15));
        uint32_t acol = (uint32_t)((lane >> 4) * 16);
        uint32_t brow = (uint32_t)(wn + ((lane >> 4) << 3) + (lane & 7));
        uint32_t bcol = (uint32_t)(((lane >> 3) & 1) * 16);
#pragma unroll
        for (int ks = 0; ks < 2; ks++) {
#pragma unroll
            for (int mi = 0; mi < 4; mi++)
                aoff[ks][mi] = SWZ64((arow + mi * 16) * 64 + ks * 32 + acol);
#pragma unroll
            for (int g = 0; g < 2; g++)
                boff[ks][g] = SWZ64((brow + g * 16) * 64 + ks * 32 + bcol);
        }
    }

    float a1[4][4][4], a2[4][4][4];
#pragma unroll
    for (int mi = 0; mi < 4; mi++)
#pragma unroll
        for (int ni = 0; ni < 4; ni++)
#pragma unroll
            for (int j = 0; j < 4; j++) { a1[mi][ni][j] = 0.0f; a2[mi][ni][j] = 0.0f; }

    const int nch = Kg / 32;
    auto load_stage = [&](int c) {
        const uint32_t st = smu + (uint32_t)(c & (NST - 1)) * STGD;
        const int k0 = c * 32;
        cpa16(st + so0,          gA + k0);
        cpa16(st + so1,          gA + k0 + rstep);
        cpa16(st + ASZ + so0,    g1 + k0);
        cpa16(st + ASZ + so1,    g1 + k0 + rstep);
        cpa16(st + 2*ASZ + so0,  g2 + k0);
        cpa16(st + 2*ASZ + so1,  g2 + k0 + rstep);
        CPC();
    };

    load_stage(0); load_stage(1); load_stage(2);

    for (int c = 0; c < nch; ++c) {
        asm volatile("cp.async.wait_group 2;" ::: "memory");
        __syncthreads();
        if (c + 3 < nch) load_stage(c + 3);

        const uint32_t st = smu + (uint32_t)(c & (NST - 1)) * STGD;
#pragma unroll
        for (int ks = 0; ks < 2; ks++) {
            uint32_t ah[4][4];
#pragma unroll
            for (int mi = 0; mi < 4; mi++)
                ldsm4(ah[mi], st + aoff[ks][mi]);
#pragma unroll
            for (int g = 0; g < 2; g++) {
                uint32_t t1[4], t2[4];
                ldsm4(t1, st + ASZ + boff[ks][g]);
                ldsm4(t2, st + 2*ASZ + boff[ks][g]);
#pragma unroll
                for (int mi = 0; mi < 4; mi++) {
                    mmaf16(a1[mi][2*g],   ah[mi], t1);
                    mmaf16(a1[mi][2*g+1], ah[mi], t1 + 2);
                    mmaf16(a2[mi][2*g],   ah[mi], t2);
                    mmaf16(a2[mi][2*g+1], ah[mi], t2 + 2);
                }
            }
        }
    }

    if (GATE == 1) {
#pragma unroll
        for (int mi = 0; mi < 4; mi++) {
            int r = bm + wm + mi * 16 + (lane >> 2);
#pragma unroll
            for (int ni = 0; ni < 4; ni++) {
                int c = bn + wn + ni * 8 + (lane & 3) * 2;
                *(uint32_t*)(O1 + (size_t)r * N + c) =
                    packh2(a1[mi][ni][0]*a2[mi][ni][0], a1[mi][ni][1]*a2[mi][ni][1]);
                *(uint32_t*)(O1 + (size_t)(r + 8) * N + c) =
                    packh2(a1[mi][ni][2]*a2[mi][ni][2], a1[mi][ni][3]*a2[mi][ni][3]);
            }
        }
    } else {
        // transpose both into [Dv][Nv] per batch via SMEM (LDS=136 halfs/row)
        size_t batch = (size_t)(bm >> 12);
        size_t base = batch * (size_t)Dv * Nv + (size_t)bn * Nv + (bm & 4095);
        __half* s16 = (__half*)sm;
        const int LDS = 136;
        const float (*accs[2])[4][4] = { a1, a2 };
        __half* outs[2] = { O1, O2 };
#pragma unroll
        for (int w = 0; w < 2; w++) {
            __syncthreads();
#pragma unroll
            for (int mi = 0; mi < 4; mi++) {
                int r = wm + mi * 16 + (lane >> 2);
#pragma unroll
                for (int ni = 0; ni < 4; ni++) {
                    int c = wn + ni * 8 + (lane & 3) * 2;
                    s16[r * LDS + c]           = __float2half_rn(accs[w][mi][ni][0]);
                    s16[r * LDS + c + 1]       = __float2half_rn(accs[w][mi][ni][1]);
                    s16[(r + 8) * LDS + c]     = __float2half_rn(accs[w][mi][ni][2]);
                    s16[(r + 8) * LDS + c + 1] = __float2half_rn(accs[w][mi][ni][3]);
                }
            }
            __syncthreads();
            int d = tid >> 1, nb = (tid & 1) * 64;
            __half* rh = outs[w] + base + (size_t)d * Nv + nb;
#pragma unroll
            for (int j = 0; j < 8; j++) {
                alignas(16) __half hb[8];
#pragma unroll
                for (int i = 0; i < 8; i++)
                    hb[i] = s16[(nb + j * 8 + i) * LDS + d];
                *(uint4*)(rh + j * 8) = *(const uint4*)hb;
            }
        }
    }
}

// --------------- single-B 1-pass GEMM (kv / out) ----------------------------
// CTA 128x256, 8 warps, warp 64x64. MODE 0: fp32 straight. MODE 1: transposed fp16.
template<int MODE>
__global__ __launch_bounds__(GT, 1)
void gemm1(const __half* __restrict__ Ag, const __half* __restrict__ Bg,
           float* __restrict__ Cf, __half* __restrict__ OH,
           int M, int N, int Kg, long sA, long sB, long sO)
{
    extern __shared__ char sm[];
    const uint32_t smu = s2u(sm);
    const int tid = threadIdx.x, lane = tid & 31, wid = tid >> 5;
    const int bm = blockIdx.y * 128, bn = blockIdx.x * 256;
    const int wm = (wid & 1) * 64, wn = (wid >> 1) * 64;

    const __half* Ap = Ag + (size_t)blockIdx.z * sA;
    const __half* Bp = Bg + (size_t)blockIdx.z * sB;

    const int rr = tid >> 2, cg = tid & 3;
    uint32_t soA[2], soB[4];
#pragma unroll
    for (int j = 0; j < 2; j++) soA[j] = SWZ64((uint32_t)((rr + j*64) * 64 + cg * 16));
#pragma unroll
    for (int j = 0; j < 4; j++) soB[j] = SWZ64((uint32_t)((rr + j*64) * 64 + cg * 16));
    const __half* gA = Ap + (size_t)(bm + rr) * Kg + cg * 8;
    const __half* gB = Bp + (size_t)(bn + rr) * Kg + cg * 8;
    const size_t rstep = (size_t)64 * Kg;

    uint32_t aoff[2][4], boff[2][4];
    {
        uint32_t arow = (uint32_t)(wm + (lane & 15));
        uint32_t acol = (uint32_t)((lane >> 4) * 16);
        uint32_t brow = (uint32_t)(wn + ((lane >> 4) << 3) + (lane & 7));
        uint32_t bcol = (uint32_t)(((lane >> 3) & 1) * 16);
#pragma unroll
        for (int ks = 0; ks < 2; ks++) {
#pragma unroll
            for (int mi = 0; mi < 4; mi++)
                aoff[ks][mi] = SWZ64((arow + mi * 16) * 64 + ks * 32 + acol);
#pragma unroll
            for (int g = 0; g < 4; g++)
                boff[ks][g] = SWZ64((brow + g * 16) * 64 + ks * 32 + bcol);
        }
    }

    float acc[4][8][4];
#pragma unroll
    for (int mi = 0; mi < 4; mi++)
#pragma unroll
        for (int ni = 0; ni < 8; ni++)
#pragma unroll
            for (int j = 0; j < 4; j++) acc[mi][ni][j] = 0.0f;

    const int nch = Kg / 32;
    auto load_stage = [&](int c) {
        const uint32_t st = smu + (uint32_t)(c & (NST - 1)) * STGS;
        const int k0 = c * 32;
#pragma unroll
        for (int j = 0; j < 2; j++)
            cpa16(st + soA[j], gA + k0 + j * rstep);
#pragma unroll
        for (int j = 0; j < 4; j++)
            cpa16(st + ASZ + soB[j], gB + k0 + j * rstep);
        CPC();
    };

    load_stage(0); load_stage(1); load_stage(2);

    for (int c = 0; c < nch; ++c) {
        asm volatile("cp.async.wait_group 2;" ::: "memory");
        __syncthreads();
        if (c + 3 < nch) load_stage(c + 3);

        const uint32_t st = smu + (uint32_t)(c & (NST - 1)) * STGS;
#pragma unroll
        for (int ks = 0; ks < 2; ks++) {
            uint32_t ah[4][4];
#pragma unroll
            for (int mi = 0; mi < 4; mi++)
                ldsm4(ah[mi], st + aoff[ks][mi]);
#pragma unroll
            for (int g = 0; g < 4; g++) {
                uint32_t tb[4];
                ldsm4(tb, st + ASZ + boff[ks][g]);
#pragma unroll
                for (int mi = 0; mi < 4; mi++) {
                    mmaf16(acc[mi][2*g],   ah[mi], tb);
                    mmaf16(acc[mi][2*g+1], ah[mi], tb + 2);
                }
            }
        }
    }

    if (MODE == 0) {
        float* Cb = Cf + (size_t)blockIdx.z * sO;
#pragma unroll
        for (int mi = 0; mi < 4; mi++) {
            int rA = bm + wm + mi * 16 + (lane >> 2);
#pragma unroll
            for (int ni = 0; ni < 8; ni++) {
                int col = bn + wn + ni * 8 + (lane & 3) * 2;
                *(float2*)(Cb + (size_t)rA * N + col)       = make_float2(acc[mi][ni][0], acc[mi][ni][1]);
                *(float2*)(Cb + (size_t)(rA + 8) * N + col) = make_float2(acc[mi][ni][2], acc[mi][ni][3]);
            }
        }
    } else {
        // transpose 128x256 tile -> fp16 rows (bn+d), cols bm.. (LDS=264 halfs)
        size_t base = (size_t)blockIdx.z * sO + (size_t)bn * M + bm;
        __half* s16 = (__half*)sm;
        const int LDS = 264;
        __syncthreads();
#pragma unroll
        for (int mi = 0; mi < 4; mi++) {
            int r = wm + mi * 16 + (lane >> 2);
#pragma unroll
            for (int ni = 0; ni < 8; ni++) {
                int c = wn + ni * 8 + (lane & 3) * 2;
                s16[r * LDS + c]           = __float2half_rn(acc[mi][ni][0]);
                s16[r * LDS + c + 1]       = __float2half_rn(acc[mi][ni][1]);
                s16[(r + 8) * LDS + c]     = __float2half_rn(acc[mi][ni][2]);
                s16[(r + 8) * LDS + c + 1] = __float2half_rn(acc[mi][ni][3]);
            }
        }
        __syncthreads();
        int d = tid;                       // 0..255 output rows
        __half* rh = OH + base + (size_t)d * M;
#pragma unroll
        for (int j = 0; j < 16; j++) {
            alignas(16) __half hb[8];
#pragma unroll
            for (int i = 0; i < 8; i++)
                hb[i] = s16[(j * 8 + i) * LDS + d];
            *(uint4*)(rh + j * 8) = *(const uint4*)hb;
        }
    }
}

// --------------------------- conversion kernels ----------------------------
__global__ void conv_x(const float* __restrict__ in, __half* __restrict__ o) {
    size_t i = (size_t)blockIdx.x * blockDim.x + threadIdx.x;
    float4 f = ((const float4*)in)[i];
    ((__half2*)o)[i*2]   = __halves2half2(__float2half_rn(f.x), __float2half_rn(f.y));
    ((__half2*)o)[i*2+1] = __halves2half2(__float2half_rn(f.z), __float2half_rn(f.w));
}

__global__ void conv_wT(const float* w0, const float* w1, const float* w2, const float* w3,
                        __half* __restrict__ O) {
    const float* in = (blockIdx.z == 0) ? w0 : (blockIdx.z == 1) ? w1
                     : (blockIdx.z == 2) ? w2 : w3;
    __half* o = O + (size_t)blockIdx.z * Dv * Dv;
    __shared__ float t[32][33];
    int c0 = blockIdx.x * 32, r0 = blockIdx.y * 32;
    int tx = threadIdx.x, ty = threadIdx.y;
#pragma unroll
    for (int i = 0; i < 4; i++)
        t[ty + i*8][tx] = in[(size_t)(r0 + ty + i*8) * Dv + c0 + tx];
    __syncthreads();
#pragma unroll
    for (int i = 0; i < 4; i++) {
        int oc = c0 + ty + i*8, od = r0 + tx;
        o[(size_t)oc * Dv + od] = __float2half_rn(t[tx][ty + i*8]);
    }
}

// ------------------------------- launch ------------------------------------
extern "C" void kernel_launch(void* const* d_in, const int* in_sizes, int n_in,
                              void* d_out, int out_size) {
    const float* x   = (const float*)d_in[0];
    const float* w[4] = { (const float*)d_in[1], (const float*)d_in[2],
                          (const float*)d_in[3], (const float*)d_in[4] };
    float* out = (float*)d_out;

    __half *X,*WT,*Q,*KT,*VT,*KVT;
    cudaGetSymbolAddress((void**)&X,   g_X);
    cudaGetSymbolAddress((void**)&WT,  g_WT);
    cudaGetSymbolAddress((void**)&Q,   g_Q);
    cudaGetSymbolAddress((void**)&KT,  g_KT);  cudaGetSymbolAddress((void**)&VT,  g_VT);
    cudaGetSymbolAddress((void**)&KVT, g_KVT);

    cudaFuncSetAttribute(gemm1_dual<0>, cudaFuncAttributeMaxDynamicSharedMemorySize, SMEMD);
    cudaFuncSetAttribute(gemm1_dual<1>, cudaFuncAttributeMaxDynamicSharedMemorySize, SMEMD);
    cudaFuncSetAttribute(gemm1<0>,      cudaFuncAttributeMaxDynamicSharedMemorySize, SMEMS);
    cudaFuncSetAttribute(gemm1<1>,      cudaFuncAttributeMaxDynamicSharedMemorySize, SMEMS);

    const size_t DDe = (size_t)Dv * Dv;
    const size_t PNe = (size_t)BNROWS * Dv;
    dim3 tb32(32, 8);

    // 1) conversions
    conv_x<<<(unsigned)(PNe/4/256), 256>>>(x, X);
    conv_wT<<<dim3(Dv/32, Dv/32, 4), tb32>>>(w[0], w[1], w[2], w[3], WT);

    // 2) q = (x@Wql)*(x@Wqr) -> straight fp16
    gemm1_dual<1><<<dim3(Dv/128, BNROWS/128), GT, SMEMD>>>(
        X, WT + 0*DDe, WT + 1*DDe, Q, nullptr, Dv, Dv);

    // 3) k, v -> k^T, v^T fp16 [Dv][Nv] per batch
    gemm1_dual<0><<<dim3(Dv/128, BNROWS/128), GT, SMEMD>>>(
        X, WT + 2*DDe, WT + 3*DDe, KT, VT, Dv, Dv);

    // 4) kv[b] = k^T@v -> kv^T fp16 [Dv][Dv]   (grid 4x8x4 = 128 CTAs, ~1 wave)
    gemm1<1><<<dim3(Dv/256, Dv/128, Bv), GT, SMEMS>>>(
        KT, VT, nullptr, KVT, Dv, Dv, Nv, (long)Dv*Nv, (long)Dv*Nv, (long)DDe);

    // 5) out[b] = q@kv -> fp32   (grid 4x32x4 = 512 CTAs)
    gemm1<0><<<dim3(Dv/256, Nv/128, Bv), GT, SMEMS>>>(
        Q, KVT, out, nullptr, Nv, Dv, Dv, (long)Nv*Dv, (long)DDe, (long)Nv*Dv);
}

// round 13
// speedup vs baseline: 5.3337x; 1.0006x over previous
#include <cuda_runtime.h>
#include <cuda_fp16.h>
#include <cstdint>

// LinearAttention B=4, N=4096, D=1024 fp32
// R13: all 1-pass fp16. Burst-ordered mainloops (all ldsm, then full MMA burst);
//      both projection jobs merged into one launch (grid.z).

#define Bv 4
#define Nv 4096
#define Dv 1024
#define BNROWS (Bv*Nv)            // 16384

#define GT 256                    // 8 warps
#define NST 4
#define ASZ  8192                 // 128 rows x 64B
#define BSZ 16384                 // 256 rows x 64B

#define STGD (3*ASZ)              // proj: A,B1,B2        (24KB)
#define SMEMD (NST*STGD)          // 98304
#define STGS (ASZ+BSZ)            // single: A(128),B(256) (24KB)
#define SMEMS (NST*STGS)          // 98304 (>= 128*264*2 epi scratch)

#define SWZ64(x) ((x) ^ (((x) >> 3) & 0x30))

// ------------------------------ scratch -----------------------------------
__device__ __align__(16) __half g_X  [(size_t)BNROWS*Dv];
__device__ __align__(16) __half g_WT [4][1024*1024];
__device__ __align__(16) __half g_Q  [(size_t)BNROWS*Dv];
__device__ __align__(16) __half g_KT [(size_t)Bv*Dv*Nv];
__device__ __align__(16) __half g_VT [(size_t)Bv*Dv*Nv];
__device__ __align__(16) __half g_KVT[(size_t)Bv*Dv*Dv];

// ------------------------------ helpers ------------------------------------
__device__ __forceinline__ uint32_t s2u(const void* p) {
    uint32_t a;
    asm("{ .reg .u64 t; cvta.to.shared.u64 t, %1; cvt.u32.u64 %0, t; }" : "=r"(a) : "l"(p));
    return a;
}
__device__ __forceinline__ void cpa16(uint32_t dst, const void* src) {
    asm volatile("cp.async.cg.shared.global [%0], [%1], 16;" :: "r"(dst), "l"(src));
}
#define CPC() asm volatile("cp.async.commit_group;" ::: "memory")

__device__ __forceinline__ void ldsm4(uint32_t* r, uint32_t addr) {
    asm volatile("ldmatrix.sync.aligned.m8n8.x4.shared.b16 {%0,%1,%2,%3}, [%4];"
                 : "=r"(r[0]), "=r"(r[1]), "=r"(r[2]), "=r"(r[3]) : "r"(addr));
}
__device__ __forceinline__ void mmaf16(float* c, const uint32_t* a, const uint32_t* b) {
    asm volatile(
        "mma.sync.aligned.m16n8k16.row.col.f32.f16.f16.f32 "
        "{%0,%1,%2,%3}, {%4,%5,%6,%7}, {%8,%9}, {%0,%1,%2,%3};"
        : "+f"(c[0]), "+f"(c[1]), "+f"(c[2]), "+f"(c[3])
        : "r"(a[0]), "r"(a[1]), "r"(a[2]), "r"(a[3]), "r"(b[0]), "r"(b[1]));
}
__device__ __forceinline__ uint32_t packh2(float f0, float f1) {
    return ((uint32_t)__half_as_ushort(__float2half_rn(f1)) << 16)
         | __half_as_ushort(__float2half_rn(f0));
}

// --------------- merged projection GEMM (both dual jobs) --------------------
// CTA 128x128, 8 warps, warp 64x32, burst-ordered.
// z=0: B=(Wql,Wqr), q = C1*C2 -> straight fp16 into Q.
// z=1: B=(Wk,Wv),  C1,C2 -> transposed fp16 into KT,VT (per-batch [Dv][Nv]).
__global__ __launch_bounds__(GT, 1)
void gemm1_proj(const __half* __restrict__ Ag,
                const __half* __restrict__ W0, const __half* __restrict__ W1,
                const __half* __restrict__ W2, const __half* __restrict__ W3,
                __half* __restrict__ Q, __half* __restrict__ KT,
                __half* __restrict__ VT, int N, int Kg)
{
    extern __shared__ char sm[];
    const uint32_t smu = s2u(sm);
    const int tid = threadIdx.x, lane = tid & 31, wid = tid >> 5;
    const int bm = blockIdx.y * 128, bn = blockIdx.x * 128;
    const int wm = (wid & 1) * 64, wn = (wid >> 1) * 32;
    const int job = blockIdx.z;

    const __half* B1 = (job == 0) ? W0 : W2;
    const __half* B2 = (job == 0) ? W1 : W3;

    const int rr = tid >> 2, cg = tid & 3;
    const uint32_t so0 = SWZ64((uint32_t)(rr * 64 + cg * 16));
    const uint32_t so1 = SWZ64((uint32_t)((rr + 64) * 64 + cg * 16));
    const __half* gA = Ag + (size_t)(bm + rr) * Kg + cg * 8;
    const __half* g1 = B1 + (size_t)(bn + rr) * Kg + cg * 8;
    const __half* g2 = B2 + (size_t)(bn + rr) * Kg + cg * 8;
    const size_t rstep = (size_t)64 * Kg;

    uint32_t aoff[2][4], boff[2][2];
    {
        uint32_t arow = (uint32_t)(wm + (lane & 15));
        uint32_t acol = (uint32_t)((lane >> 4) * 16);
        uint32_t brow = (uint32_t)(wn + ((lane >> 4) << 3) + (lane & 7));
        uint32_t bcol = (uint32_t)(((lane >> 3) & 1) * 16);
#pragma unroll
        for (int ks = 0; ks < 2; ks++) {
#pragma unroll
            for (int mi = 0; mi < 4; mi++)
                aoff[ks][mi] = SWZ64((arow + mi * 16) * 64 + ks * 32 + acol);
#pragma unroll
            for (int g = 0; g < 2; g++)
                boff[ks][g] = SWZ64((brow + g * 16) * 64 + ks * 32 + bcol);
        }
    }

    float a1[4][4][4], a2[4][4][4];
#pragma unroll
    for (int mi = 0; mi < 4; mi++)
#pragma unroll
        for (int ni = 0; ni < 4; ni++)
#pragma unroll
            for (int j = 0; j < 4; j++) { a1[mi][ni][j] = 0.0f; a2[mi][ni][j] = 0.0f; }

    const int nch = Kg / 32;
    auto load_stage = [&](int c) {
        const uint32_t st = smu + (uint32_t)(c & (NST - 1)) * STGD;
        const int k0 = c * 32;
        cpa16(st + so0,          gA + k0);
        cpa16(st + so1,          gA + k0 + rstep);
        cpa16(st + ASZ + so0,    g1 + k0);
        cpa16(st + ASZ + so1,    g1 + k0 + rstep);
        cpa16(st + 2*ASZ + so0,  g2 + k0);
        cpa16(st + 2*ASZ + so1,  g2 + k0 + rstep);
        CPC();
    };

    load_stage(0); load_stage(1); load_stage(2);

    for (int c = 0; c < nch; ++c) {
        asm volatile("cp.async.wait_group 2;" ::: "memory");
        __syncthreads();
        if (c + 3 < nch) load_stage(c + 3);

        const uint32_t st = smu + (uint32_t)(c & (NST - 1)) * STGD;
#pragma unroll
        for (int ks = 0; ks < 2; ks++) {
            // ---- load ALL operands for this ks-step ----
            uint32_t ah[4][4], t1[2][4], t2[2][4];
#pragma unroll
            for (int mi = 0; mi < 4; mi++)
                ldsm4(ah[mi], st + aoff[ks][mi]);
#pragma unroll
            for (int g = 0; g < 2; g++) {
                ldsm4(t1[g], st + ASZ + boff[ks][g]);
                ldsm4(t2[g], st + 2*ASZ + boff[ks][g]);
            }
            // ---- one uninterrupted 32-MMA burst, 2 independent chains ----
#pragma unroll
            for (int g = 0; g < 2; g++)
#pragma unroll
                for (int mi = 0; mi < 4; mi++) {
                    mmaf16(a1[mi][2*g],   ah[mi], t1[g]);
                    mmaf16(a1[mi][2*g+1], ah[mi], t1[g] + 2);
                    mmaf16(a2[mi][2*g],   ah[mi], t2[g]);
                    mmaf16(a2[mi][2*g+1], ah[mi], t2[g] + 2);
                }
        }
    }

    if (job == 0) {
        // q = C1*C2 -> straight fp16
#pragma unroll
        for (int mi = 0; mi < 4; mi++) {
            int r = bm + wm + mi * 16 + (lane >> 2);
#pragma unroll
            for (int ni = 0; ni < 4; ni++) {
                int c = bn + wn + ni * 8 + (lane & 3) * 2;
                *(uint32_t*)(Q + (size_t)r * N + c) =
                    packh2(a1[mi][ni][0]*a2[mi][ni][0], a1[mi][ni][1]*a2[mi][ni][1]);
                *(uint32_t*)(Q + (size_t)(r + 8) * N + c) =
                    packh2(a1[mi][ni][2]*a2[mi][ni][2], a1[mi][ni][3]*a2[mi][ni][3]);
            }
        }
    } else {
        // transpose both into [Dv][Nv] per batch via SMEM (LDS=136 halfs/row)
        size_t batch = (size_t)(bm >> 12);
        size_t base = batch * (size_t)Dv * Nv + (size_t)bn * Nv + (bm & 4095);
        __half* s16 = (__half*)sm;
        const int LDS = 136;
        const float (*accs[2])[4][4] = { a1, a2 };
        __half* outs[2] = { KT, VT };
#pragma unroll
        for (int w = 0; w < 2; w++) {
            __syncthreads();
#pragma unroll
            for (int mi = 0; mi < 4; mi++) {
                int r = wm + mi * 16 + (lane >> 2);
#pragma unroll
                for (int ni = 0; ni < 4; ni++) {
                    int c = wn + ni * 8 + (lane & 3) * 2;
                    s16[r * LDS + c]           = __float2half_rn(accs[w][mi][ni][0]);
                    s16[r * LDS + c + 1]       = __float2half_rn(accs[w][mi][ni][1]);
                    s16[(r + 8) * LDS + c]     = __float2half_rn(accs[w][mi][ni][2]);
                    s16[(r + 8) * LDS + c + 1] = __float2half_rn(accs[w][mi][ni][3]);
                }
            }
            __syncthreads();
            int d = tid >> 1, nb = (tid & 1) * 64;
            __half* rh = outs[w] + base + (size_t)d * Nv + nb;
#pragma unroll
            for (int j = 0; j < 8; j++) {
                alignas(16) __half hb[8];
#pragma unroll
                for (int i = 0; i < 8; i++)
                    hb[i] = s16[(nb + j * 8 + i) * LDS + d];
                *(uint4*)(rh + j * 8) = *(const uint4*)hb;
            }
        }
    }
}

// --------------- single-B 1-pass GEMM (kv / out), burst-ordered -------------
// CTA 128x256, 8 warps, warp 64x64. MODE 0: fp32 straight. MODE 1: transposed fp16.
template<int MODE>
__global__ __launch_bounds__(GT, 1)
void gemm1(const __half* __restrict__ Ag, const __half* __restrict__ Bg,
           float* __restrict__ Cf, __half* __restrict__ OH,
           int M, int N, int Kg, long sA, long sB, long sO)
{
    extern __shared__ char sm[];
    const uint32_t smu = s2u(sm);
    const int tid = threadIdx.x, lane = tid & 31, wid = tid >> 5;
    const int bm = blockIdx.y * 128, bn = blockIdx.x * 256;
    const int wm = (wid & 1) * 64, wn = (wid >> 1) * 64;

    const __half* Ap = Ag + (size_t)blockIdx.z * sA;
    const __half* Bp = Bg + (size_t)blockIdx.z * sB;

    const int rr = tid >> 2, cg = tid & 3;
    uint32_t soA[2], soB[4];
#pragma unroll
    for (int j = 0; j < 2; j++) soA[j] = SWZ64((uint32_t)((rr + j*64) * 64 + cg * 16));
#pragma unroll
    for (int j = 0; j < 4; j++) soB[j] = SWZ64((uint32_t)((rr + j*64) * 64 + cg * 16));
    const __half* gA = Ap + (size_t)(bm + rr) * Kg + cg * 8;
    const __half* gB = Bp + (size_t)(bn + rr) * Kg + cg * 8;
    const size_t rstep = (size_t)64 * Kg;

    uint32_t aoff[2][4], boff[2][4];
    {
        uint32_t arow = (uint32_t)(wm + (lane & 15));
        uint32_t acol = (uint32_t)((lane >> 4) * 16);
        uint32_t brow = (uint32_t)(wn + ((lane >> 4) << 3) + (lane & 7));
        uint32_t bcol = (uint32_t)(((lane >> 3) & 1) * 16);
#pragma unroll
        for (int ks = 0; ks < 2; ks++) {
#pragma unroll
            for (int mi = 0; mi < 4; mi++)
                aoff[ks][mi] = SWZ64((arow + mi * 16) * 64 + ks * 32 + acol);
#pragma unroll
            for (int g = 0; g < 4; g++)
                boff[ks][g] = SWZ64((brow + g * 16) * 64 + ks * 32 + bcol);
        }
    }

    float acc[4][8][4];
#pragma unroll
    for (int mi = 0; mi < 4; mi++)
#pragma unroll
        for (int ni = 0; ni < 8; ni++)
#pragma unroll
            for (int j = 0; j < 4; j++) acc[mi][ni][j] = 0.0f;

    const int nch = Kg / 32;
    auto load_stage = [&](int c) {
        const uint32_t st = smu + (uint32_t)(c & (NST - 1)) * STGS;
        const int k0 = c * 32;
#pragma unroll
        for (int j = 0; j < 2; j++)
            cpa16(st + soA[j], gA + k0 + j * rstep);
#pragma unroll
        for (int j = 0; j < 4; j++)
            cpa16(st + ASZ + soB[j], gB + k0 + j * rstep);
        CPC();
    };

    load_stage(0); load_stage(1); load_stage(2);

    for (int c = 0; c < nch; ++c) {
        asm volatile("cp.async.wait_group 2;" ::: "memory");
        __syncthreads();
        if (c + 3 < nch) load_stage(c + 3);

        const uint32_t st = smu + (uint32_t)(c & (NST - 1)) * STGS;
#pragma unroll
        for (int ks = 0; ks < 2; ks++) {
            // ---- load ALL operands ----
            uint32_t ah[4][4], tb[4][4];
#pragma unroll
            for (int mi = 0; mi < 4; mi++)
                ldsm4(ah[mi], st + aoff[ks][mi]);
#pragma unroll
            for (int g = 0; g < 4; g++)
                ldsm4(tb[g], st + ASZ + boff[ks][g]);
            // ---- 32-MMA burst ----
#pragma unroll
            for (int g = 0; g < 4; g++)
#pragma unroll
                for (int mi = 0; mi < 4; mi++) {
                    mmaf16(acc[mi][2*g],   ah[mi], tb[g]);
                    mmaf16(acc[mi][2*g+1], ah[mi], tb[g] + 2);
                }
        }
    }

    if (MODE == 0) {
        float* Cb = Cf + (size_t)blockIdx.z * sO;
#pragma unroll
        for (int mi = 0; mi < 4; mi++) {
            int rA = bm + wm + mi * 16 + (lane >> 2);
#pragma unroll
            for (int ni = 0; ni < 8; ni++) {
                int col = bn + wn + ni * 8 + (lane & 3) * 2;
                *(float2*)(Cb + (size_t)rA * N + col)       = make_float2(acc[mi][ni][0], acc[mi][ni][1]);
                *(float2*)(Cb + (size_t)(rA + 8) * N + col) = make_float2(acc[mi][ni][2], acc[mi][ni][3]);
            }
        }
    } else {
        // transpose 128x256 tile -> fp16 rows (bn+d), cols bm.. (LDS=264 halfs)
        size_t base = (size_t)blockIdx.z * sO + (size_t)bn * M + bm;
        __half* s16 = (__half*)sm;
        const int LDS = 264;
        __syncthreads();
#pragma unroll
        for (int mi = 0; mi < 4; mi++) {
            int r = wm + mi * 16 + (lane >> 2);
#pragma unroll
            for (int ni = 0; ni < 8; ni++) {
                int c = wn + ni * 8 + (lane & 3) * 2;
                s16[r * LDS + c]           = __float2half_rn(acc[mi][ni][0]);
                s16[r * LDS + c + 1]       = __float2half_rn(acc[mi][ni][1]);
                s16[(r + 8) * LDS + c]     = __float2half_rn(acc[mi][ni][2]);
                s16[(r + 8) * LDS + c + 1] = __float2half_rn(acc[mi][ni][3]);
            }
        }
        __syncthreads();
        int d = tid;                       // 0..255 output rows
        __half* rh = OH + base + (size_t)d * M;
#pragma unroll
        for (int j = 0; j < 16; j++) {
            alignas(16) __half hb[8];
#pragma unroll
            for (int i = 0; i < 8; i++)
                hb[i] = s16[(j * 8 + i) * LDS + d];
            *(uint4*)(rh + j * 8) = *(const uint4*)hb;
        }
    }
}

// --------------------------- conversion kernels ----------------------------
__global__ void conv_x(const float* __restrict__ in, __half* __restrict__ o) {
    size_t i = (size_t)blockIdx.x * blockDim.x + threadIdx.x;
    float4 f = ((const float4*)in)[i];
    ((__half2*)o)[i*2]   = __halves2half2(__float2half_rn(f.x), __float2half_rn(f.y));
    ((__half2*)o)[i*2+1] = __halves2half2(__float2half_rn(f.z), __float2half_rn(f.w));
}

__global__ void conv_wT(const float* w0, const float* w1, const float* w2, const float* w3,
                        __half* __restrict__ O) {
    const float* in = (blockIdx.z == 0) ? w0 : (blockIdx.z == 1) ? w1
                     : (blockIdx.z == 2) ? w2 : w3;
    __half* o = O + (size_t)blockIdx.z * Dv * Dv;
    __shared__ float t[32][33];
    int c0 = blockIdx.x * 32, r0 = blockIdx.y * 32;
    int tx = threadIdx.x, ty = threadIdx.y;
#pragma unroll
    for (int i = 0; i < 4; i++)
        t[ty + i*8][tx] = in[(size_t)(r0 + ty + i*8) * Dv + c0 + tx];
    __syncthreads();
#pragma unroll
    for (int i = 0; i < 4; i++) {
        int oc = c0 + ty + i*8, od = r0 + tx;
        o[(size_t)oc * Dv + od] = __float2half_rn(t[tx][ty + i*8]);
    }
}

// ------------------------------- launch ------------------------------------
extern "C" void kernel_launch(void* const* d_in, const int* in_sizes, int n_in,
                              void* d_out, int out_size) {
    const float* x   = (const float*)d_in[0];
    const float* w[4] = { (const float*)d_in[1], (const float*)d_in[2],
                          (const float*)d_in[3], (const float*)d_in[4] };
    float* out = (float*)d_out;

    __half *X,*WT,*Q,*KT,*VT,*KVT;
    cudaGetSymbolAddress((void**)&X,   g_X);
    cudaGetSymbolAddress((void**)&WT,  g_WT);
    cudaGetSymbolAddress((void**)&Q,   g_Q);
    cudaGetSymbolAddress((void**)&KT,  g_KT);  cudaGetSymbolAddress((void**)&VT,  g_VT);
    cudaGetSymbolAddress((void**)&KVT, g_KVT);

    cudaFuncSetAttribute(gemm1_proj, cudaFuncAttributeMaxDynamicSharedMemorySize, SMEMD);
    cudaFuncSetAttribute(gemm1<0>,   cudaFuncAttributeMaxDynamicSharedMemorySize, SMEMS);
    cudaFuncSetAttribute(gemm1<1>,   cudaFuncAttributeMaxDynamicSharedMemorySize, SMEMS);

    const size_t DDe = (size_t)Dv * Dv;
    const size_t PNe = (size_t)BNROWS * Dv;
    dim3 tb32(32, 8);

    // 1) conversions
    conv_x<<<(unsigned)(PNe/4/256), 256>>>(x, X);
    conv_wT<<<dim3(Dv/32, Dv/32, 4), tb32>>>(w[0], w[1], w[2], w[3], WT);

    // 2) all four projections in ONE launch (z=0: q gate; z=1: k/v transpose)
    gemm1_proj<<<dim3(Dv/128, BNROWS/128, 2), GT, SMEMD>>>(
        X, WT + 0*DDe, WT + 1*DDe, WT + 2*DDe, WT + 3*DDe,
        Q, KT, VT, Dv, Dv);

    // 3) kv[b] = k^T@v -> kv^T fp16 [Dv][Dv]
    gemm1<1><<<dim3(Dv/256, Dv/128, Bv), GT, SMEMS>>>(
        KT, VT, nullptr, KVT, Dv, Dv, Nv, (long)Dv*Nv, (long)Dv*Nv, (long)DDe);

    // 4) out[b] = q@kv -> fp32
    gemm1<0><<<dim3(Dv/256, Nv/128, Bv), GT, SMEMS>>>(
        Q, KVT, out, nullptr, Nv, Dv, Dv, (long)Nv*Dv, (long)DDe, (long)Nv*Dv);
}

// round 14
// speedup vs baseline: 6.2074x; 1.1638x over previous
#include <cuda_runtime.h>
#include <cuda_fp16.h>
#include <cstdint>

// LinearAttention B=4, N=4096, D=1024 fp32
// R14: all 1-pass fp16; 2 CTAs/SM (independent barrier domains) via
//      __launch_bounds__(256,2): proj CTA 128x64, kv/out CTA 128x128.
//      Pipeline tail waits fixed (2/1/0).

#define Bv 4
#define Nv 4096
#define Dv 1024
#define BNROWS (Bv*Nv)            // 16384

#define GT 256                    // 8 warps
#define NST 4
#define STG 16384                 // 16KB stage (both kernel families)
#define SMEMB (NST*STG)           // 65536

#define SWZ64(x) ((x) ^ (((x) >> 3) & 0x30))

// ------------------------------ scratch -----------------------------------
__device__ __align__(16) __half g_X  [(size_t)BNROWS*Dv];
__device__ __align__(16) __half g_WT [4][1024*1024];
__device__ __align__(16) __half g_Q  [(size_t)BNROWS*Dv];
__device__ __align__(16) __half g_KT [(size_t)Bv*Dv*Nv];
__device__ __align__(16) __half g_VT [(size_t)Bv*Dv*Nv];
__device__ __align__(16) __half g_KVT[(size_t)Bv*Dv*Dv];

// ------------------------------ helpers ------------------------------------
__device__ __forceinline__ uint32_t s2u(const void* p) {
    uint32_t a;
    asm("{ .reg .u64 t; cvta.to.shared.u64 t, %1; cvt.u32.u64 %0, t; }" : "=r"(a) : "l"(p));
    return a;
}
__device__ __forceinline__ void cpa16(uint32_t dst, const void* src) {
    asm volatile("cp.async.cg.shared.global [%0], [%1], 16;" :: "r"(dst), "l"(src));
}
#define CPC() asm volatile("cp.async.commit_group;" ::: "memory")
#define WAITG(n) asm volatile("cp.async.wait_group %0;" :: "n"(n) : "memory")

__device__ __forceinline__ void ldsm4(uint32_t* r, uint32_t addr) {
    asm volatile("ldmatrix.sync.aligned.m8n8.x4.shared.b16 {%0,%1,%2,%3}, [%4];"
                 : "=r"(r[0]), "=r"(r[1]), "=r"(r[2]), "=r"(r[3]) : "r"(addr));
}
__device__ __forceinline__ void mmaf16(float* c, const uint32_t* a, const uint32_t* b) {
    asm volatile(
        "mma.sync.aligned.m16n8k16.row.col.f32.f16.f16.f32 "
        "{%0,%1,%2,%3}, {%4,%5,%6,%7}, {%8,%9}, {%0,%1,%2,%3};"
        : "+f"(c[0]), "+f"(c[1]), "+f"(c[2]), "+f"(c[3])
        : "r"(a[0]), "r"(a[1]), "r"(a[2]), "r"(a[3]), "r"(b[0]), "r"(b[1]));
}
__device__ __forceinline__ uint32_t packh2(float f0, float f1) {
    return ((uint32_t)__half_as_ushort(__float2half_rn(f1)) << 16)
         | __half_as_ushort(__float2half_rn(f0));
}

// --------------- merged projection GEMM (dual-B, CTA 128x64) ----------------
// 8 warps, warp 32x32 per output. z=0: q=C1*C2 straight fp16.
// z=1: C1,C2 -> transposed fp16 into KT,VT (per-batch [Dv][Nv]).
__global__ __launch_bounds__(GT, 2)
void gemm1_proj(const __half* __restrict__ Ag,
                const __half* __restrict__ W0, const __half* __restrict__ W1,
                const __half* __restrict__ W2, const __half* __restrict__ W3,
                __half* __restrict__ Q, __half* __restrict__ KT,
                __half* __restrict__ VT, int N, int Kg)
{
    extern __shared__ char sm[];
    const uint32_t smu = s2u(sm);
    const int tid = threadIdx.x, lane = tid & 31, wid = tid >> 5;
    const int bm = blockIdx.y * 128, bn = blockIdx.x * 64;
    const int wm = (wid & 3) * 32, wn = (wid >> 2) * 32;
    const int job = blockIdx.z;

    const __half* B1 = (job == 0) ? W0 : W2;
    const __half* B2 = (job == 0) ? W1 : W3;

    const int rr = tid >> 2, cg = tid & 3;                 // rr 0..63
    const uint32_t so0 = SWZ64((uint32_t)(rr * 64 + cg * 16));
    const uint32_t so1 = SWZ64((uint32_t)((rr + 64) * 64 + cg * 16));
    const __half* gA = Ag + (size_t)(bm + rr) * Kg + cg * 8;
    const __half* g1 = B1 + (size_t)(bn + rr) * Kg + cg * 8;
    const __half* g2 = B2 + (size_t)(bn + rr) * Kg + cg * 8;
    const size_t rstep = (size_t)64 * Kg;

    uint32_t aoff[2][2], boff[2][2];
    {
        uint32_t arow = (uint32_t)(wm + (lane & 15));
        uint32_t acol = (uint32_t)((lane >> 4) * 16);
        uint32_t brow = (uint32_t)(wn + ((lane >> 4) << 3) + (lane & 7));
        uint32_t bcol = (uint32_t)(((lane >> 3) & 1) * 16);
#pragma unroll
        for (int ks = 0; ks < 2; ks++) {
#pragma unroll
            for (int mi = 0; mi < 2; mi++)
                aoff[ks][mi] = SWZ64((arow + mi * 16) * 64 + ks * 32 + acol);
#pragma unroll
            for (int g = 0; g < 2; g++)
                boff[ks][g] = SWZ64((brow + g * 16) * 64 + ks * 32 + bcol);
        }
    }

    float a1[2][4][4], a2[2][4][4];
#pragma unroll
    for (int mi = 0; mi < 2; mi++)
#pragma unroll
        for (int ni = 0; ni < 4; ni++)
#pragma unroll
            for (int j = 0; j < 4; j++) { a1[mi][ni][j] = 0.0f; a2[mi][ni][j] = 0.0f; }

    const int nch = Kg / 32;
    auto load_stage = [&](int c) {
        const uint32_t st = smu + (uint32_t)(c & (NST - 1)) * STG;
        const int k0 = c * 32;
        cpa16(st + so0,           gA + k0);                // A rows 0..63
        cpa16(st + so1,           gA + k0 + rstep);        // A rows 64..127
        cpa16(st + 8192 + so0,    g1 + k0);                // B1 (64 rows)
        cpa16(st + 12288 + so0,   g2 + k0);                // B2
        CPC();
    };

    load_stage(0); load_stage(1); load_stage(2);

    for (int c = 0; c < nch; ++c) {
        if (c + 3 <= nch)      WAITG(2);
        else if (c + 2 == nch) WAITG(1);
        else                   WAITG(0);
        __syncthreads();
        if (c + 3 < nch) load_stage(c + 3);

        const uint32_t st = smu + (uint32_t)(c & (NST - 1)) * STG;
#pragma unroll
        for (int ks = 0; ks < 2; ks++) {
            uint32_t ah[2][4], t1[2][4], t2[2][4];
#pragma unroll
            for (int mi = 0; mi < 2; mi++)
                ldsm4(ah[mi], st + aoff[ks][mi]);
#pragma unroll
            for (int g = 0; g < 2; g++) {
                ldsm4(t1[g], st + 8192 + boff[ks][g]);
                ldsm4(t2[g], st + 12288 + boff[ks][g]);
            }
#pragma unroll
            for (int g = 0; g < 2; g++)
#pragma unroll
                for (int mi = 0; mi < 2; mi++) {
                    mmaf16(a1[mi][2*g],   ah[mi], t1[g]);
                    mmaf16(a1[mi][2*g+1], ah[mi], t1[g] + 2);
                    mmaf16(a2[mi][2*g],   ah[mi], t2[g]);
                    mmaf16(a2[mi][2*g+1], ah[mi], t2[g] + 2);
                }
        }
    }

    if (job == 0) {
        // q = C1*C2 -> straight fp16
#pragma unroll
        for (int mi = 0; mi < 2; mi++) {
            int r = bm + wm + mi * 16 + (lane >> 2);
#pragma unroll
            for (int ni = 0; ni < 4; ni++) {
                int c = bn + wn + ni * 8 + (lane & 3) * 2;
                *(uint32_t*)(Q + (size_t)r * N + c) =
                    packh2(a1[mi][ni][0]*a2[mi][ni][0], a1[mi][ni][1]*a2[mi][ni][1]);
                *(uint32_t*)(Q + (size_t)(r + 8) * N + c) =
                    packh2(a1[mi][ni][2]*a2[mi][ni][2], a1[mi][ni][3]*a2[mi][ni][3]);
            }
        }
    } else {
        // transpose both 128x64 tiles into [Dv][Nv] per batch (LDS=72 halfs/row)
        size_t batch = (size_t)(bm >> 12);
        size_t base = batch * (size_t)Dv * Nv + (size_t)bn * Nv + (bm & 4095);
        __half* s16 = (__half*)sm;
        const int LDS = 72;
        const float (*accs[2])[4][4] = { a1, a2 };
        __half* outs[2] = { KT, VT };
#pragma unroll
        for (int w = 0; w < 2; w++) {
            __syncthreads();
#pragma unroll
            for (int mi = 0; mi < 2; mi++) {
                int r = wm + mi * 16 + (lane >> 2);
#pragma unroll
                for (int ni = 0; ni < 4; ni++) {
                    int c = wn + ni * 8 + (lane & 3) * 2;
                    s16[r * LDS + c]           = __float2half_rn(accs[w][mi][ni][0]);
                    s16[r * LDS + c + 1]       = __float2half_rn(accs[w][mi][ni][1]);
                    s16[(r + 8) * LDS + c]     = __float2half_rn(accs[w][mi][ni][2]);
                    s16[(r + 8) * LDS + c + 1] = __float2half_rn(accs[w][mi][ni][3]);
                }
            }
            __syncthreads();
            int d = tid >> 2, nb = (tid & 3) * 32;          // d 0..63, 32 cols each
            __half* rh = outs[w] + base + (size_t)d * Nv + nb;
#pragma unroll
            for (int j = 0; j < 4; j++) {
                alignas(16) __half hb[8];
#pragma unroll
                for (int i = 0; i < 8; i++)
                    hb[i] = s16[(nb + j * 8 + i) * LDS + d];
                *(uint4*)(rh + j * 8) = *(const uint4*)hb;
            }
        }
    }
}

// --------------- single-B 1-pass GEMM (kv / out), CTA 128x128 ---------------
// 8 warps, warp 32x64. MODE 0: fp32 straight. MODE 1: transposed fp16.
template<int MODE>
__global__ __launch_bounds__(GT, 2)
void gemm1(const __half* __restrict__ Ag, const __half* __restrict__ Bg,
           float* __restrict__ Cf, __half* __restrict__ OH,
           int M, int N, int Kg, long sA, long sB, long sO)
{
    extern __shared__ char sm[];
    const uint32_t smu = s2u(sm);
    const int tid = threadIdx.x, lane = tid & 31, wid = tid >> 5;
    const int bm = blockIdx.y * 128, bn = blockIdx.x * 128;
    const int wm = (wid & 3) * 32, wn = (wid >> 2) * 64;

    const __half* Ap = Ag + (size_t)blockIdx.z * sA;
    const __half* Bp = Bg + (size_t)blockIdx.z * sB;

    const int rr = tid >> 2, cg = tid & 3;
    const uint32_t so0 = SWZ64((uint32_t)(rr * 64 + cg * 16));
    const uint32_t so1 = SWZ64((uint32_t)((rr + 64) * 64 + cg * 16));
    const __half* gA = Ap + (size_t)(bm + rr) * Kg + cg * 8;
    const __half* gB = Bp + (size_t)(bn + rr) * Kg + cg * 8;
    const size_t rstep = (size_t)64 * Kg;

    uint32_t aoff[2][2], boff[2][4];
    {
        uint32_t arow = (uint32_t)(wm + (lane & 15));
        uint32_t acol = (uint32_t)((lane >> 4) * 16);
        uint32_t brow = (uint32_t)(wn + ((lane >> 4) << 3) + (lane & 7));
        uint32_t bcol = (uint32_t)(((lane >> 3) & 1) * 16);
#pragma unroll
        for (int ks = 0; ks < 2; ks++) {
#pragma unroll
            for (int mi = 0; mi < 2; mi++)
                aoff[ks][mi] = SWZ64((arow + mi * 16) * 64 + ks * 32 + acol);
#pragma unroll
            for (int g = 0; g < 4; g++)
                boff[ks][g] = SWZ64((brow + g * 16) * 64 + ks * 32 + bcol);
        }
    }

    float acc[2][8][4];
#pragma unroll
    for (int mi = 0; mi < 2; mi++)
#pragma unroll
        for (int ni = 0; ni < 8; ni++)
#pragma unroll
            for (int j = 0; j < 4; j++) acc[mi][ni][j] = 0.0f;

    const int nch = Kg / 32;
    auto load_stage = [&](int c) {
        const uint32_t st = smu + (uint32_t)(c & (NST - 1)) * STG;
        const int k0 = c * 32;
        cpa16(st + so0,         gA + k0);
        cpa16(st + so1,         gA + k0 + rstep);
        cpa16(st + 8192 + so0,  gB + k0);
        cpa16(st + 8192 + so1,  gB + k0 + rstep);
        CPC();
    };

    load_stage(0); load_stage(1); load_stage(2);

    for (int c = 0; c < nch; ++c) {
        if (c + 3 <= nch)      WAITG(2);
        else if (c + 2 == nch) WAITG(1);
        else                   WAITG(0);
        __syncthreads();
        if (c + 3 < nch) load_stage(c + 3);

        const uint32_t st = smu + (uint32_t)(c & (NST - 1)) * STG;
#pragma unroll
        for (int ks = 0; ks < 2; ks++) {
            uint32_t ah[2][4], tb[4][4];
#pragma unroll
            for (int mi = 0; mi < 2; mi++)
                ldsm4(ah[mi], st + aoff[ks][mi]);
#pragma unroll
            for (int g = 0; g < 4; g++)
                ldsm4(tb[g], st + 8192 + boff[ks][g]);
#pragma unroll
            for (int g = 0; g < 4; g++)
#pragma unroll
                for (int mi = 0; mi < 2; mi++) {
                    mmaf16(acc[mi][2*g],   ah[mi], tb[g]);
                    mmaf16(acc[mi][2*g+1], ah[mi], tb[g] + 2);
                }
        }
    }

    if (MODE == 0) {
        float* Cb = Cf + (size_t)blockIdx.z * sO;
#pragma unroll
        for (int mi = 0; mi < 2; mi++) {
            int rA = bm + wm + mi * 16 + (lane >> 2);
#pragma unroll
            for (int ni = 0; ni < 8; ni++) {
                int col = bn + wn + ni * 8 + (lane & 3) * 2;
                *(float2*)(Cb + (size_t)rA * N + col)       = make_float2(acc[mi][ni][0], acc[mi][ni][1]);
                *(float2*)(Cb + (size_t)(rA + 8) * N + col) = make_float2(acc[mi][ni][2], acc[mi][ni][3]);
            }
        }
    } else {
        // transpose 128x128 tile -> fp16 rows (bn+d), cols bm.. (LDS=136 halfs)
        size_t base = (size_t)blockIdx.z * sO + (size_t)bn * M + bm;
        __half* s16 = (__half*)sm;
        const int LDS = 136;
        __syncthreads();
#pragma unroll
        for (int mi = 0; mi < 2; mi++) {
            int r = wm + mi * 16 + (lane >> 2);
#pragma unroll
            for (int ni = 0; ni < 8; ni++) {
                int c = wn + ni * 8 + (lane & 3) * 2;
                s16[r * LDS + c]           = __float2half_rn(acc[mi][ni][0]);
                s16[r * LDS + c + 1]       = __float2half_rn(acc[mi][ni][1]);
                s16[(r + 8) * LDS + c]     = __float2half_rn(acc[mi][ni][2]);
                s16[(r + 8) * LDS + c + 1] = __float2half_rn(acc[mi][ni][3]);
            }
        }
        __syncthreads();
        int d = tid >> 1, nb = (tid & 1) * 64;              // d 0..127, 64 cols each
        __half* rh = OH + base + (size_t)d * M + nb;
#pragma unroll
        for (int j = 0; j < 8; j++) {
            alignas(16) __half hb[8];
#pragma unroll
            for (int i = 0; i < 8; i++)
                hb[i] = s16[(nb + j * 8 + i) * LDS + d];
            *(uint4*)(rh + j * 8) = *(const uint4*)hb;
        }
    }
}

// --------------------------- conversion kernels ----------------------------
__global__ void conv_x(const float* __restrict__ in, __half* __restrict__ o) {
    size_t i = (size_t)blockIdx.x * blockDim.x + threadIdx.x;
    float4 f = ((const float4*)in)[i];
    ((__half2*)o)[i*2]   = __halves2half2(__float2half_rn(f.x), __float2half_rn(f.y));
    ((__half2*)o)[i*2+1] = __halves2half2(__float2half_rn(f.z), __float2half_rn(f.w));
}

__global__ void conv_wT(const float* w0, const float* w1, const float* w2, const float* w3,
                        __half* __restrict__ O) {
    const float* in = (blockIdx.z == 0) ? w0 : (blockIdx.z == 1) ? w1
                     : (blockIdx.z == 2) ? w2 : w3;
    __half* o = O + (size_t)blockIdx.z * Dv * Dv;
    __shared__ float t[32][33];
    int c0 = blockIdx.x * 32, r0 = blockIdx.y * 32;
    int tx = threadIdx.x, ty = threadIdx.y;
#pragma unroll
    for (int i = 0; i < 4; i++)
        t[ty + i*8][tx] = in[(size_t)(r0 + ty + i*8) * Dv + c0 + tx];
    __syncthreads();
#pragma unroll
    for (int i = 0; i < 4; i++) {
        int oc = c0 + ty + i*8, od = r0 + tx;
        o[(size_t)oc * Dv + od] = __float2half_rn(t[tx][ty + i*8]);
    }
}

// ------------------------------- launch ------------------------------------
extern "C" void kernel_launch(void* const* d_in, const int* in_sizes, int n_in,
                              void* d_out, int out_size) {
    const float* x   = (const float*)d_in[0];
    const float* w[4] = { (const float*)d_in[1], (const float*)d_in[2],
                          (const float*)d_in[3], (const float*)d_in[4] };
    float* out = (float*)d_out;

    __half *X,*WT,*Q,*KT,*VT,*KVT;
    cudaGetSymbolAddress((void**)&X,   g_X);
    cudaGetSymbolAddress((void**)&WT,  g_WT);
    cudaGetSymbolAddress((void**)&Q,   g_Q);
    cudaGetSymbolAddress((void**)&KT,  g_KT);  cudaGetSymbolAddress((void**)&VT,  g_VT);
    cudaGetSymbolAddress((void**)&KVT, g_KVT);

    cudaFuncSetAttribute(gemm1_proj, cudaFuncAttributeMaxDynamicSharedMemorySize, SMEMB);
    cudaFuncSetAttribute(gemm1<0>,   cudaFuncAttributeMaxDynamicSharedMemorySize, SMEMB);
    cudaFuncSetAttribute(gemm1<1>,   cudaFuncAttributeMaxDynamicSharedMemorySize, SMEMB);

    const size_t DDe = (size_t)Dv * Dv;
    const size_t PNe = (size_t)BNROWS * Dv;
    dim3 tb32(32, 8);

    // 1) conversions
    conv_x<<<(unsigned)(PNe/4/256), 256>>>(x, X);
    conv_wT<<<dim3(Dv/32, Dv/32, 4), tb32>>>(w[0], w[1], w[2], w[3], WT);

    // 2) all four projections in ONE launch (z=0: q gate; z=1: k/v transpose)
    gemm1_proj<<<dim3(Dv/64, BNROWS/128, 2), GT, SMEMB>>>(
        X, WT + 0*DDe, WT + 1*DDe, WT + 2*DDe, WT + 3*DDe,
        Q, KT, VT, Dv, Dv);

    // 3) kv[b] = k^T@v -> kv^T fp16 [Dv][Dv]  (256 CTAs = one 2-occ wave)
    gemm1<1><<<dim3(Dv/128, Dv/128, Bv), GT, SMEMB>>>(
        KT, VT, nullptr, KVT, Dv, Dv, Nv, (long)Dv*Nv, (long)Dv*Nv, (long)DDe);

    // 4) out[b] = q@kv -> fp32
    gemm1<0><<<dim3(Dv/128, Nv/128, Bv), GT, SMEMB>>>(
        Q, KVT, out, nullptr, Nv, Dv, Dv, (long)Nv*Dv, (long)DDe, (long)Nv*Dv);
}